// round 1
// baseline (speedup 1.0000x reference)
#include <cuda_runtime.h>
#include <math.h>

// ---------------- problem constants ----------------
constexpr int CB  = 2;
constexpr int CS  = 1024;
constexpr int CD  = 2048;
constexpr int CH  = 16;
constexpr int CKVH= 4;
constexpr int CHD = 128;
constexpr int CE  = 64;
constexpr int CK  = 8;     // top-k
constexpr int CF  = 768;
constexpr int CT  = CB * CS;            // 2048 tokens
constexpr float CEPS = 1e-6f;
constexpr int NSLOT = CT * CK;          // 16384

// ---------------- scratch (device globals; no allocation allowed) ----------------
__device__ float g_h   [CT * CD];            // rmsnorm1 out
__device__ float g_q   [CT * CH  * CHD];     // q proj
__device__ float g_k   [CT * CKVH* CHD];     // k proj
__device__ float g_v   [CT * CKVH* CHD];     // v proj
__device__ float g_o   [CT * CH  * CHD];     // attn out
__device__ float g_ht  [CT * CD];            // rmsnorm2 out
__device__ float g_logits[CT * CE];
__device__ int   g_topi[CT * CK];
__device__ float g_topw[CT * CK];
__device__ int   g_counts[CE];
__device__ int   g_offsets[CE];
__device__ int   g_cursor[CE];
__device__ int   g_slot_token[NSLOT];
__device__ int   g_pos_of[NSLOT];            // (t,k) -> slot position
__device__ float g_act [NSLOT * CF];         // silu(g)*u
__device__ float g_y   [(size_t)NSLOT * CD]; // down output per slot

// ---------------- rmsnorm (row of D=2048) ----------------
__global__ void rmsnorm_kernel(const float* __restrict__ in,
                               const float* __restrict__ w,
                               float* __restrict__ out) {
    int t = blockIdx.x;
    const float* row = in + (size_t)t * CD;
    float ss = 0.f;
    for (int d = threadIdx.x; d < CD; d += 256) { float v = row[d]; ss += v * v; }
    __shared__ float red[256];
    red[threadIdx.x] = ss; __syncthreads();
    for (int st = 128; st > 0; st >>= 1) {
        if (threadIdx.x < st) red[threadIdx.x] += red[threadIdx.x + st];
        __syncthreads();
    }
    float scale = rsqrtf(red[0] / (float)CD + CEPS);
    for (int d = threadIdx.x; d < CD; d += 256)
        out[(size_t)t * CD + d] = row[d] * scale * w[d];
}

// ---------------- generic fp32 GEMM: C[M,N] = A[M,K] @ B[K,N] (+res) ----------------
// tiles 64x64x16, 256 threads, 4x4 per thread. M,N multiples of 64; K multiple of 16.
__global__ void gemm64(const float* __restrict__ A, const float* __restrict__ Bm,
                       const float* __restrict__ res, float* __restrict__ C,
                       int M, int N, int K) {
    __shared__ float As[16][65];
    __shared__ float Bs[16][64];
    int tid = threadIdx.x;
    int tx = tid & 15, ty = tid >> 4;
    int m0 = blockIdx.y * 64, n0 = blockIdx.x * 64;
    int arow = tid >> 2;
    int acol = (tid & 3) * 4;
    int blin = tid * 4;
    int brow = blin >> 6;
    int bcol = blin & 63;
    const float* Aptr = A + (size_t)(m0 + arow) * K + acol;
    const float* Bptr = Bm + (size_t)brow * N + n0 + bcol;
    float acc[4][4] = {};
    for (int k0 = 0; k0 < K; k0 += 16) {
        float4 av = *(const float4*)(Aptr + k0);
        float4 bv = *(const float4*)(Bptr + (size_t)k0 * N);
        As[acol + 0][arow] = av.x; As[acol + 1][arow] = av.y;
        As[acol + 2][arow] = av.z; As[acol + 3][arow] = av.w;
        *(float4*)&Bs[brow][bcol] = bv;
        __syncthreads();
#pragma unroll
        for (int kk = 0; kk < 16; kk++) {
            float a[4], b[4];
#pragma unroll
            for (int i = 0; i < 4; i++) a[i] = As[kk][ty * 4 + i];
#pragma unroll
            for (int j = 0; j < 4; j++) b[j] = Bs[kk][tx * 4 + j];
#pragma unroll
            for (int i = 0; i < 4; i++)
#pragma unroll
                for (int j = 0; j < 4; j++) acc[i][j] += a[i] * b[j];
        }
        __syncthreads();
    }
#pragma unroll
    for (int i = 0; i < 4; i++)
#pragma unroll
        for (int j = 0; j < 4; j++) {
            size_t idx = (size_t)(m0 + ty * 4 + i) * N + n0 + tx * 4 + j;
            C[idx] = acc[i][j] + (res ? res[idx] : 0.f);
        }
}

// ---------------- per-head q/k rmsnorm + rope ----------------
__global__ void qknorm_rope_kernel(const float* __restrict__ cos_,
                                   const float* __restrict__ sin_,
                                   const float* __restrict__ qn_w,
                                   const float* __restrict__ kn_w) {
    int t = blockIdx.x;
    int hy = blockIdx.y;      // 0..H+KVH-1
    int d = threadIdx.x;      // 0..127
    float* ptr; const float* w;
    if (hy < CH) { ptr = g_q + ((size_t)t * CH + hy) * CHD;          w = qn_w; }
    else         { ptr = g_k + ((size_t)t * CKVH + (hy - CH)) * CHD; w = kn_w; }
    float v = ptr[d];
    float ss = v * v;
#pragma unroll
    for (int off = 16; off > 0; off >>= 1) ss += __shfl_xor_sync(0xffffffffu, ss, off);
    __shared__ float ws[4];
    if ((d & 31) == 0) ws[d >> 5] = ss;
    __syncthreads();
    float tot = ws[0] + ws[1] + ws[2] + ws[3];
    float nrm = v * rsqrtf(tot / (float)CHD + CEPS) * w[d];
    __shared__ float nbuf[128];
    nbuf[d] = nrm;
    __syncthreads();
    float rot = (d < 64) ? -nbuf[d + 64] : nbuf[d - 64];
    float c = cos_[(size_t)t * CHD + d];
    float s = sin_[(size_t)t * CHD + d];
    ptr[d] = nrm * c + rot * s;
}

// ---------------- flash attention (causal, GQA), 32q x 32k tiles ----------------
__global__ void attn_kernel() {
    int qt = blockIdx.x;          // query tile (S/32)
    int h  = blockIdx.y;
    int b  = blockIdx.z;
    int kvh = h / (CH / CKVH);
    int tid = threadIdx.x;        // 128
    int r  = tid >> 2;            // 0..31 query row in tile
    int qd = tid & 3;             // quarter
    __shared__ float Qs[32][128];
    __shared__ float KVs[32][128];
    __shared__ float Ss[32][33];

    for (int i = tid; i < 32 * 128; i += 128) {
        int rr = i >> 7, dd = i & 127;
        Qs[rr][dd] = g_q[((size_t)(b * CS + qt * 32 + rr) * CH + h) * CHD + dd];
    }
    float acc[32];
#pragma unroll
    for (int i = 0; i < 32; i++) acc[i] = 0.f;
    float m = -1e30f, l = 0.f;
    const float scale = 0.088388347648318447f;   // 1/sqrt(128)

    for (int jt = 0; jt <= qt; jt++) {
        __syncthreads();   // KVs reuse safety
        for (int i = tid; i < 32 * 128; i += 128) {
            int rr = i >> 7, dd = i & 127;
            KVs[rr][dd] = g_k[((size_t)(b * CS + jt * 32 + rr) * CKVH + kvh) * CHD + dd];
        }
        __syncthreads();
        // scores for row r, cols qd*8 .. qd*8+7
        float sc[8];
#pragma unroll
        for (int jj = 0; jj < 8; jj++) sc[jj] = 0.f;
        for (int dd = 0; dd < 128; dd++) {
            float qv = Qs[r][dd];
#pragma unroll
            for (int jj = 0; jj < 8; jj++) sc[jj] += qv * KVs[qd * 8 + jj][dd];
        }
        int qg = qt * 32 + r;
#pragma unroll
        for (int jj = 0; jj < 8; jj++) {
            int kg = jt * 32 + qd * 8 + jj;
            float v = sc[jj] * scale;
            if (kg > qg) v = -1e30f;
            Ss[r][qd * 8 + jj] = v;
        }
        __syncthreads();
        // online softmax: each thread handles full row r (redundant x4, consistent)
        float tm = m;
#pragma unroll
        for (int c = 0; c < 32; c++) tm = fmaxf(tm, Ss[r][c]);
        float alpha = expf(m - tm);
        float p[32];
        float lsum = 0.f;
#pragma unroll
        for (int c = 0; c < 32; c++) { p[c] = expf(Ss[r][c] - tm); lsum += p[c]; }
        l = l * alpha + lsum;
        m = tm;
        __syncthreads();   // done reading Ss and KVs(K)
        for (int i = tid; i < 32 * 128; i += 128) {
            int rr = i >> 7, dd = i & 127;
            KVs[rr][dd] = g_v[((size_t)(b * CS + jt * 32 + rr) * CKVH + kvh) * CHD + dd];
        }
        __syncthreads();
#pragma unroll
        for (int dd = 0; dd < 32; dd++) acc[dd] *= alpha;
        for (int c = 0; c < 32; c++) {
            float pv = p[c];
#pragma unroll
            for (int dd = 0; dd < 32; dd++) acc[dd] += pv * KVs[c][qd * 32 + dd];
        }
    }
    float inv = 1.f / l;
    int t = b * CS + qt * 32 + r;
#pragma unroll
    for (int dd = 0; dd < 32; dd++)
        g_o[((size_t)t * CH + h) * CHD + qd * 32 + dd] = acc[dd] * inv;
}

// ---------------- router softmax + top-8 (matches jax tie-break: lowest idx) ----------------
__global__ void topk_kernel() {
    int t = blockIdx.x, e = threadIdx.x;   // 64 threads
    __shared__ float red[64];
    __shared__ int   redi[64];
    __shared__ float tv[8];
    __shared__ int   ti[8];
    float lg = g_logits[t * CE + e];
    red[e] = lg; __syncthreads();
    for (int st = 32; st > 0; st >>= 1) {
        if (e < st) red[e] = fmaxf(red[e], red[e + st]);
        __syncthreads();
    }
    float mx = red[0]; __syncthreads();
    float ex = expf(lg - mx);
    red[e] = ex; __syncthreads();
    for (int st = 32; st > 0; st >>= 1) {
        if (e < st) red[e] += red[e + st];
        __syncthreads();
    }
    float sum = red[0]; __syncthreads();
    float sel = ex / sum;
    for (int k = 0; k < 8; k++) {
        red[e] = sel; redi[e] = e; __syncthreads();
        for (int st = 32; st > 0; st >>= 1) {
            if (e < st) {
                if (red[e + st] > red[e]) { red[e] = red[e + st]; redi[e] = redi[e + st]; }
            }
            __syncthreads();
        }
        if (e == 0) { tv[k] = red[0]; ti[k] = redi[0]; }
        __syncthreads();
        if (e == ti[k]) sel = -1.f;
        __syncthreads();
    }
    if (e < 8) {
        float s8 = 0.f;
#pragma unroll
        for (int k = 0; k < 8; k++) s8 += tv[k];
        g_topi[t * CK + e] = ti[e];
        g_topw[t * CK + e] = tv[e] / s8;
    }
}

// ---------------- routing bookkeeping ----------------
__global__ void zero_counts_kernel() { if (threadIdx.x < CE) g_counts[threadIdx.x] = 0; }

__global__ void count_kernel() {
    int i = blockIdx.x * blockDim.x + threadIdx.x;
    if (i < NSLOT) atomicAdd(&g_counts[g_topi[i]], 1);
}

__global__ void scan_kernel() {
    int acc = 0;
    for (int e = 0; e < CE; e++) {
        g_offsets[e] = acc;
        g_cursor[e]  = acc;
        acc += g_counts[e];
    }
}

__global__ void fill_kernel() {
    int i = blockIdx.x * blockDim.x + threadIdx.x;
    if (i < NSLOT) {
        int e = g_topi[i];
        int p = atomicAdd(&g_cursor[e], 1);
        g_slot_token[p] = i >> 3;      // token index
        g_pos_of[i] = p;               // deterministic combine map
    }
}

// ---------------- MoE gate+up GEMM with gather + silu epilogue ----------------
// grid: (F/64, E); loops row tiles of 64 slots
__global__ void moe_gateup_kernel(const float* __restrict__ w_gate,
                                  const float* __restrict__ w_up) {
    int e = blockIdx.y;
    int n0 = blockIdx.x * 64;
    int off = g_offsets[e], cnt = g_counts[e];
    const float* BG = w_gate + (size_t)e * CD * CF;
    const float* BU = w_up   + (size_t)e * CD * CF;
    __shared__ float As[16][65];
    __shared__ float BsG[16][64];
    __shared__ float BsU[16][64];
    int tid = threadIdx.x;
    int tx = tid & 15, ty = tid >> 4;
    int arow = tid >> 2;
    int acol = (tid & 3) * 4;
    int blin = tid * 4;
    int brow = blin >> 6;
    int bcol = blin & 63;

    for (int rt = 0; rt * 64 < cnt; rt++) {
        int row = rt * 64 + arow;
        int tok = (row < cnt) ? g_slot_token[off + row] : 0;
        const float* Arow = g_ht + (size_t)tok * CD + acol;
        float accG[4][4] = {}, accU[4][4] = {};
        for (int k0 = 0; k0 < CD; k0 += 16) {
            float4 av = *(const float4*)(Arow + k0);
            As[acol + 0][arow] = av.x; As[acol + 1][arow] = av.y;
            As[acol + 2][arow] = av.z; As[acol + 3][arow] = av.w;
            float4 gv = *(const float4*)(BG + (size_t)(k0 + brow) * CF + n0 + bcol);
            float4 uv = *(const float4*)(BU + (size_t)(k0 + brow) * CF + n0 + bcol);
            *(float4*)&BsG[brow][bcol] = gv;
            *(float4*)&BsU[brow][bcol] = uv;
            __syncthreads();
#pragma unroll
            for (int kk = 0; kk < 16; kk++) {
                float a[4], bg[4], bu[4];
#pragma unroll
                for (int i = 0; i < 4; i++) a[i] = As[kk][ty * 4 + i];
#pragma unroll
                for (int j = 0; j < 4; j++) { bg[j] = BsG[kk][tx * 4 + j]; bu[j] = BsU[kk][tx * 4 + j]; }
#pragma unroll
                for (int i = 0; i < 4; i++)
#pragma unroll
                    for (int j = 0; j < 4; j++) {
                        accG[i][j] += a[i] * bg[j];
                        accU[i][j] += a[i] * bu[j];
                    }
            }
            __syncthreads();
        }
#pragma unroll
        for (int i = 0; i < 4; i++) {
            int srow = rt * 64 + ty * 4 + i;
            if (srow < cnt) {
#pragma unroll
                for (int j = 0; j < 4; j++) {
                    float g = accG[i][j], u = accU[i][j];
                    float s = g / (1.f + expf(-g));       // silu
                    g_act[(size_t)(off + srow) * CF + n0 + tx * 4 + j] = s * u;
                }
            }
        }
    }
}

// ---------------- MoE down GEMM: y[slot] = act[slot] @ w_down[e] ----------------
// grid: (D/64, E)
__global__ void moe_down_kernel(const float* __restrict__ w_down) {
    int e = blockIdx.y;
    int n0 = blockIdx.x * 64;
    int off = g_offsets[e], cnt = g_counts[e];
    const float* Bm = w_down + (size_t)e * CF * CD;
    __shared__ float As[16][65];
    __shared__ float Bs[16][64];
    int tid = threadIdx.x;
    int tx = tid & 15, ty = tid >> 4;
    int arow = tid >> 2;
    int acol = (tid & 3) * 4;
    int blin = tid * 4;
    int brow = blin >> 6;
    int bcol = blin & 63;

    for (int rt = 0; rt * 64 < cnt; rt++) {
        int row = rt * 64 + arow;
        int srcrow = (row < cnt) ? row : (cnt - 1);
        const float* Arow = g_act + (size_t)(off + srcrow) * CF + acol;
        float acc[4][4] = {};
        for (int k0 = 0; k0 < CF; k0 += 16) {
            float4 av = *(const float4*)(Arow + k0);
            As[acol + 0][arow] = av.x; As[acol + 1][arow] = av.y;
            As[acol + 2][arow] = av.z; As[acol + 3][arow] = av.w;
            float4 bv = *(const float4*)(Bm + (size_t)(k0 + brow) * CD + n0 + bcol);
            *(float4*)&Bs[brow][bcol] = bv;
            __syncthreads();
#pragma unroll
            for (int kk = 0; kk < 16; kk++) {
                float a[4], b[4];
#pragma unroll
                for (int i = 0; i < 4; i++) a[i] = As[kk][ty * 4 + i];
#pragma unroll
                for (int j = 0; j < 4; j++) b[j] = Bs[kk][tx * 4 + j];
#pragma unroll
                for (int i = 0; i < 4; i++)
#pragma unroll
                    for (int j = 0; j < 4; j++) acc[i][j] += a[i] * b[j];
            }
            __syncthreads();
        }
#pragma unroll
        for (int i = 0; i < 4; i++) {
            int srow = rt * 64 + ty * 4 + i;
            if (srow < cnt) {
#pragma unroll
                for (int j = 0; j < 4; j++)
                    g_y[(size_t)(off + srow) * CD + n0 + tx * 4 + j] = acc[i][j];
            }
        }
    }
}

// ---------------- final combine: out[t] += sum_k w_k * y[pos(t,k)] ----------------
__global__ void final_add_kernel(float* __restrict__ out) {
    int t = blockIdx.x;
    __shared__ int   pos[8];
    __shared__ float w[8];
    if (threadIdx.x < 8) {
        pos[threadIdx.x] = g_pos_of[t * CK + threadIdx.x];
        w[threadIdx.x]   = g_topw[t * CK + threadIdx.x];
    }
    __syncthreads();
    for (int d = threadIdx.x; d < CD; d += 256) {
        float acc = out[(size_t)t * CD + d];
#pragma unroll
        for (int k = 0; k < 8; k++)
            acc += w[k] * g_y[(size_t)pos[k] * CD + d];
        out[(size_t)t * CD + d] = acc;
    }
}

// ---------------- launch ----------------
extern "C" void kernel_launch(void* const* d_in, const int* in_sizes, int n_in,
                              void* d_out, int out_size) {
    const float* x        = (const float*)d_in[0];
    const float* cos_     = (const float*)d_in[1];
    const float* sin_     = (const float*)d_in[2];
    const float* ln1_w    = (const float*)d_in[3];
    const float* wq       = (const float*)d_in[4];
    const float* wk       = (const float*)d_in[5];
    const float* wv       = (const float*)d_in[6];
    const float* wo       = (const float*)d_in[7];
    const float* qn_w     = (const float*)d_in[8];
    const float* kn_w     = (const float*)d_in[9];
    const float* ln2_w    = (const float*)d_in[10];
    const float* router_w = (const float*)d_in[11];
    const float* w_gate   = (const float*)d_in[12];
    const float* w_up     = (const float*)d_in[13];
    const float* w_down   = (const float*)d_in[14];
    float* out = (float*)d_out;

    float *p_h, *p_q, *p_k, *p_v, *p_o, *p_ht, *p_logits;
    cudaGetSymbolAddress((void**)&p_h,  g_h);
    cudaGetSymbolAddress((void**)&p_q,  g_q);
    cudaGetSymbolAddress((void**)&p_k,  g_k);
    cudaGetSymbolAddress((void**)&p_v,  g_v);
    cudaGetSymbolAddress((void**)&p_o,  g_o);
    cudaGetSymbolAddress((void**)&p_ht, g_ht);
    cudaGetSymbolAddress((void**)&p_logits, g_logits);

    // 1. h = rmsnorm(x)
    rmsnorm_kernel<<<CT, 256>>>(x, ln1_w, p_h);
    // 2. q,k,v projections
    gemm64<<<dim3((CH * CHD) / 64, CT / 64), 256>>>(p_h, wq, nullptr, p_q, CT, CH * CHD, CD);
    gemm64<<<dim3((CKVH * CHD) / 64, CT / 64), 256>>>(p_h, wk, nullptr, p_k, CT, CKVH * CHD, CD);
    gemm64<<<dim3((CKVH * CHD) / 64, CT / 64), 256>>>(p_h, wv, nullptr, p_v, CT, CKVH * CHD, CD);
    // 3. per-head q/k rmsnorm + rope
    qknorm_rope_kernel<<<dim3(CT, CH + CKVH), 128>>>(cos_, sin_, qn_w, kn_w);
    // 4. attention
    attn_kernel<<<dim3(CS / 32, CH, CB), 128>>>();
    // 5. out = o @ wo + x  (residual)
    gemm64<<<dim3(CD / 64, CT / 64), 256>>>(p_o, wo, x, out, CT, CD, CD);
    // 6. ht = rmsnorm(out)
    rmsnorm_kernel<<<CT, 256>>>(out, ln2_w, p_ht);
    // 7. router logits + top-8
    gemm64<<<dim3(CE / 64, CT / 64), 256>>>(p_ht, router_w, nullptr, p_logits, CT, CE, CD);
    topk_kernel<<<CT, 64>>>();
    // 8. routing bookkeeping (counting sort into per-expert ranges)
    zero_counts_kernel<<<1, 64>>>();
    count_kernel<<<NSLOT / 256, 256>>>();
    scan_kernel<<<1, 1>>>();
    fill_kernel<<<NSLOT / 256, 256>>>();
    // 9. expert gate/up + silu
    moe_gateup_kernel<<<dim3(CF / 64, CE), 256>>>(w_gate, w_up);
    // 10. expert down
    moe_down_kernel<<<dim3(CD / 64, CE), 256>>>(w_down);
    // 11. deterministic per-token combine
    final_add_kernel<<<CT, 256>>>(out);
}

// round 2
// speedup vs baseline: 1.0670x; 1.0670x over previous
#include <cuda_runtime.h>
#include <math.h>
#include <mma.h>
using namespace nvcuda;

// ---------------- problem constants ----------------
constexpr int CB  = 2;
constexpr int CS  = 1024;
constexpr int CD  = 2048;
constexpr int CH  = 16;
constexpr int CKVH= 4;
constexpr int CHD = 128;
constexpr int CE  = 64;
constexpr int CK  = 8;     // top-k
constexpr int CF  = 768;
constexpr int CT  = CB * CS;            // 2048 tokens
constexpr float CEPS = 1e-6f;
constexpr int NSLOT = CT * CK;          // 16384
constexpr int PADTOT = NSLOT + CE * 128; // padded slot bound (24576)

// ---------------- scratch (device globals; no allocation allowed) ----------------
__device__ float g_h   [CT * CD];
__device__ float g_q   [CT * CH  * CHD];
__device__ float g_k   [CT * CKVH* CHD];
__device__ float g_v   [CT * CKVH* CHD];
__device__ float g_o   [CT * CH  * CHD];
__device__ float g_ht  [CT * CD];
__device__ float g_logits[CT * CE];
__device__ int   g_topi[CT * CK];
__device__ float g_topw[CT * CK];
__device__ int   g_counts[CE];
__device__ int   g_offsets[CE];       // padded offsets
__device__ int   g_cursor[CE];
__device__ int   g_slot_token[PADTOT];
__device__ int   g_pos_of[NSLOT];
__device__ float g_act [(size_t)PADTOT * CF];
__device__ float g_y   [(size_t)PADTOT * CD];

// ---------------- rmsnorm ----------------
__global__ void rmsnorm_kernel(const float* __restrict__ in,
                               const float* __restrict__ w,
                               float* __restrict__ out) {
    int t = blockIdx.x;
    const float* row = in + (size_t)t * CD;
    float ss = 0.f;
    for (int d = threadIdx.x; d < CD; d += 256) { float v = row[d]; ss += v * v; }
    __shared__ float red[256];
    red[threadIdx.x] = ss; __syncthreads();
    for (int st = 128; st > 0; st >>= 1) {
        if (threadIdx.x < st) red[threadIdx.x] += red[threadIdx.x + st];
        __syncthreads();
    }
    float scale = rsqrtf(red[0] / (float)CD + CEPS);
    for (int d = threadIdx.x; d < CD; d += 256)
        out[(size_t)t * CD + d] = row[d] * scale * w[d];
}

// ---------------- scalar GEMM (kept for router: exact fp32 feeds top-k) -------
__global__ void gemm64(const float* __restrict__ A, const float* __restrict__ Bm,
                       const float* __restrict__ res, float* __restrict__ C,
                       int M, int N, int K) {
    __shared__ float As[16][65];
    __shared__ float Bs[16][64];
    int tid = threadIdx.x;
    int tx = tid & 15, ty = tid >> 4;
    int m0 = blockIdx.y * 64, n0 = blockIdx.x * 64;
    int arow = tid >> 2;
    int acol = (tid & 3) * 4;
    int blin = tid * 4;
    int brow = blin >> 6;
    int bcol = blin & 63;
    const float* Aptr = A + (size_t)(m0 + arow) * K + acol;
    const float* Bptr = Bm + (size_t)brow * N + n0 + bcol;
    float acc[4][4] = {};
    for (int k0 = 0; k0 < K; k0 += 16) {
        float4 av = *(const float4*)(Aptr + k0);
        float4 bv = *(const float4*)(Bptr + (size_t)k0 * N);
        As[acol + 0][arow] = av.x; As[acol + 1][arow] = av.y;
        As[acol + 2][arow] = av.z; As[acol + 3][arow] = av.w;
        *(float4*)&Bs[brow][bcol] = bv;
        __syncthreads();
#pragma unroll
        for (int kk = 0; kk < 16; kk++) {
            float a[4], b[4];
#pragma unroll
            for (int i = 0; i < 4; i++) a[i] = As[kk][ty * 4 + i];
#pragma unroll
            for (int j = 0; j < 4; j++) b[j] = Bs[kk][tx * 4 + j];
#pragma unroll
            for (int i = 0; i < 4; i++)
#pragma unroll
                for (int j = 0; j < 4; j++) acc[i][j] += a[i] * b[j];
        }
        __syncthreads();
    }
#pragma unroll
    for (int i = 0; i < 4; i++)
#pragma unroll
        for (int j = 0; j < 4; j++) {
            size_t idx = (size_t)(m0 + ty * 4 + i) * N + n0 + tx * 4 + j;
            C[idx] = acc[i][j] + (res ? res[idx] : 0.f);
        }
}

// ---------------- TF32 tensor-core GEMM building blocks ----------------
using FragA = wmma::fragment<wmma::matrix_a, 16, 16, 8, wmma::precision::tf32, wmma::row_major>;
using FragB = wmma::fragment<wmma::matrix_b, 16, 16, 8, wmma::precision::tf32, wmma::row_major>;
using FragC = wmma::fragment<wmma::accumulator, 16, 16, 8, float>;

__device__ __forceinline__ void ld_a(FragA& f, const float* p, int ld) {
    wmma::load_matrix_sync(f, p, ld);
#pragma unroll
    for (int i = 0; i < f.num_elements; i++) f.x[i] = wmma::__float_to_tf32(f.x[i]);
}
__device__ __forceinline__ void ld_b(FragB& f, const float* p, int ld) {
    wmma::load_matrix_sync(f, p, ld);
#pragma unroll
    for (int i = 0; i < f.num_elements; i++) f.x[i] = wmma::__float_to_tf32(f.x[i]);
}

// dense C[M,N] = A[M,K] @ B[K,N] (+res). BM=128, BN=64, BK=32, 256 threads.
// M%128==0, N%64==0, K%32==0.
__global__ void gemm_tf32(const float* __restrict__ A, const float* __restrict__ B,
                          const float* __restrict__ res, float* __restrict__ C,
                          int M, int N, int K) {
    __shared__ float As[128][36];
    __shared__ float Bs[32][68];
    int tid = threadIdx.x;
    int w = tid >> 5;
    int wm = w & 3, wn = w >> 2;          // 4 x 2 warps, warp tile 32x32
    int m0 = blockIdx.y * 128, n0 = blockIdx.x * 64;

    FragC acc[2][2];
#pragma unroll
    for (int i = 0; i < 2; i++)
#pragma unroll
        for (int j = 0; j < 2; j++) wmma::fill_fragment(acc[i][j], 0.f);

    for (int k0 = 0; k0 < K; k0 += 32) {
#pragma unroll
        for (int it = 0; it < 4; it++) {
            int i = tid + it * 256;
            int row = i >> 3, c4 = (i & 7) * 4;
            *(float4*)&As[row][c4] = *(const float4*)&A[(size_t)(m0 + row) * K + k0 + c4];
        }
#pragma unroll
        for (int it = 0; it < 2; it++) {
            int i = tid + it * 256;
            int row = i >> 4, c4 = (i & 15) * 4;
            *(float4*)&Bs[row][c4] = *(const float4*)&B[(size_t)(k0 + row) * N + n0 + c4];
        }
        __syncthreads();
#pragma unroll
        for (int kk = 0; kk < 4; kk++) {
            FragA a[2]; FragB b[2];
#pragma unroll
            for (int i = 0; i < 2; i++) ld_a(a[i], &As[wm * 32 + i * 16][kk * 8], 36);
#pragma unroll
            for (int j = 0; j < 2; j++) ld_b(b[j], &Bs[kk * 8][wn * 32 + j * 16], 68);
#pragma unroll
            for (int i = 0; i < 2; i++)
#pragma unroll
                for (int j = 0; j < 2; j++) wmma::mma_sync(acc[i][j], a[i], b[j], acc[i][j]);
        }
        __syncthreads();
    }
#pragma unroll
    for (int i = 0; i < 2; i++)
#pragma unroll
        for (int j = 0; j < 2; j++) {
            size_t co = (size_t)(m0 + wm * 32 + i * 16) * N + n0 + wn * 32 + j * 16;
            if (res) {
                FragC r;
                wmma::load_matrix_sync(r, res + co, N, wmma::mem_row_major);
#pragma unroll
                for (int e2 = 0; e2 < r.num_elements; e2++) acc[i][j].x[e2] += r.x[e2];
            }
            wmma::store_matrix_sync(C + co, acc[i][j], N, wmma::mem_row_major);
        }
}

// ---------------- per-head q/k rmsnorm + rope ----------------
__global__ void qknorm_rope_kernel(const float* __restrict__ cos_,
                                   const float* __restrict__ sin_,
                                   const float* __restrict__ qn_w,
                                   const float* __restrict__ kn_w) {
    int t = blockIdx.x;
    int hy = blockIdx.y;
    int d = threadIdx.x;
    float* ptr; const float* w;
    if (hy < CH) { ptr = g_q + ((size_t)t * CH + hy) * CHD;          w = qn_w; }
    else         { ptr = g_k + ((size_t)t * CKVH + (hy - CH)) * CHD; w = kn_w; }
    float v = ptr[d];
    float ss = v * v;
#pragma unroll
    for (int off = 16; off > 0; off >>= 1) ss += __shfl_xor_sync(0xffffffffu, ss, off);
    __shared__ float ws[4];
    if ((d & 31) == 0) ws[d >> 5] = ss;
    __syncthreads();
    float tot = ws[0] + ws[1] + ws[2] + ws[3];
    float nrm = v * rsqrtf(tot / (float)CHD + CEPS) * w[d];
    __shared__ float nbuf[128];
    nbuf[d] = nrm;
    __syncthreads();
    float rot = (d < 64) ? -nbuf[d + 64] : nbuf[d - 64];
    float c = cos_[(size_t)t * CHD + d];
    float s = sin_[(size_t)t * CHD + d];
    ptr[d] = nrm * c + rot * s;
}

// ---------------- flash attention (causal, GQA) ----------------
__global__ void attn_kernel() {
    int qt = blockIdx.x;
    int h  = blockIdx.y;
    int b  = blockIdx.z;
    int kvh = h / (CH / CKVH);
    int tid = threadIdx.x;
    int r  = tid >> 2;
    int qd = tid & 3;
    __shared__ float Qs[32][128];
    __shared__ float KVs[32][128];
    __shared__ float Ss[32][33];

    for (int i = tid; i < 32 * 128; i += 128) {
        int rr = i >> 7, dd = i & 127;
        Qs[rr][dd] = g_q[((size_t)(b * CS + qt * 32 + rr) * CH + h) * CHD + dd];
    }
    float acc[32];
#pragma unroll
    for (int i = 0; i < 32; i++) acc[i] = 0.f;
    float m = -1e30f, l = 0.f;
    const float scale = 0.088388347648318447f;

    for (int jt = 0; jt <= qt; jt++) {
        __syncthreads();
        for (int i = tid; i < 32 * 128; i += 128) {
            int rr = i >> 7, dd = i & 127;
            KVs[rr][dd] = g_k[((size_t)(b * CS + jt * 32 + rr) * CKVH + kvh) * CHD + dd];
        }
        __syncthreads();
        float sc[8];
#pragma unroll
        for (int jj = 0; jj < 8; jj++) sc[jj] = 0.f;
        for (int dd = 0; dd < 128; dd++) {
            float qv = Qs[r][dd];
#pragma unroll
            for (int jj = 0; jj < 8; jj++) sc[jj] += qv * KVs[qd * 8 + jj][dd];
        }
        int qg = qt * 32 + r;
#pragma unroll
        for (int jj = 0; jj < 8; jj++) {
            int kg = jt * 32 + qd * 8 + jj;
            float v = sc[jj] * scale;
            if (kg > qg) v = -1e30f;
            Ss[r][qd * 8 + jj] = v;
        }
        __syncthreads();
        float tm = m;
#pragma unroll
        for (int c = 0; c < 32; c++) tm = fmaxf(tm, Ss[r][c]);
        float alpha = expf(m - tm);
        float p[32];
        float lsum = 0.f;
#pragma unroll
        for (int c = 0; c < 32; c++) { p[c] = expf(Ss[r][c] - tm); lsum += p[c]; }
        l = l * alpha + lsum;
        m = tm;
        __syncthreads();
        for (int i = tid; i < 32 * 128; i += 128) {
            int rr = i >> 7, dd = i & 127;
            KVs[rr][dd] = g_v[((size_t)(b * CS + jt * 32 + rr) * CKVH + kvh) * CHD + dd];
        }
        __syncthreads();
#pragma unroll
        for (int dd = 0; dd < 32; dd++) acc[dd] *= alpha;
        for (int c = 0; c < 32; c++) {
            float pv = p[c];
#pragma unroll
            for (int dd = 0; dd < 32; dd++) acc[dd] += pv * KVs[c][qd * 32 + dd];
        }
    }
    float inv = 1.f / l;
    int t = b * CS + qt * 32 + r;
#pragma unroll
    for (int dd = 0; dd < 32; dd++)
        g_o[((size_t)t * CH + h) * CHD + qd * 32 + dd] = acc[dd] * inv;
}

// ---------------- router softmax + top-8 ----------------
__global__ void topk_kernel() {
    int t = blockIdx.x, e = threadIdx.x;
    __shared__ float red[64];
    __shared__ int   redi[64];
    __shared__ float tv[8];
    __shared__ int   ti[8];
    float lg = g_logits[t * CE + e];
    red[e] = lg; __syncthreads();
    for (int st = 32; st > 0; st >>= 1) {
        if (e < st) red[e] = fmaxf(red[e], red[e + st]);
        __syncthreads();
    }
    float mx = red[0]; __syncthreads();
    float ex = expf(lg - mx);
    red[e] = ex; __syncthreads();
    for (int st = 32; st > 0; st >>= 1) {
        if (e < st) red[e] += red[e + st];
        __syncthreads();
    }
    float sum = red[0]; __syncthreads();
    float sel = ex / sum;
    for (int k = 0; k < 8; k++) {
        red[e] = sel; redi[e] = e; __syncthreads();
        for (int st = 32; st > 0; st >>= 1) {
            if (e < st) {
                if (red[e + st] > red[e]) { red[e] = red[e + st]; redi[e] = redi[e + st]; }
            }
            __syncthreads();
        }
        if (e == 0) { tv[k] = red[0]; ti[k] = redi[0]; }
        __syncthreads();
        if (e == ti[k]) sel = -1.f;
        __syncthreads();
    }
    if (e < 8) {
        float s8 = 0.f;
#pragma unroll
        for (int k = 0; k < 8; k++) s8 += tv[k];
        g_topi[t * CK + e] = ti[e];
        g_topw[t * CK + e] = tv[e] / s8;
    }
}

// ---------------- routing bookkeeping (padded to 128 rows per expert) --------
__global__ void zero_counts_kernel() { if (threadIdx.x < CE) g_counts[threadIdx.x] = 0; }

__global__ void count_kernel() {
    int i = blockIdx.x * blockDim.x + threadIdx.x;
    if (i < NSLOT) atomicAdd(&g_counts[g_topi[i]], 1);
}

__global__ void scan_kernel() {
    int acc = 0;
    for (int e = 0; e < CE; e++) {
        g_offsets[e] = acc;
        g_cursor[e]  = acc;
        acc += ((g_counts[e] + 127) >> 7) << 7;   // pad to 128
    }
}

__global__ void init_slots_kernel() {
    int i = blockIdx.x * blockDim.x + threadIdx.x;
    if (i < PADTOT) g_slot_token[i] = 0;
}

__global__ void fill_kernel() {
    int i = blockIdx.x * blockDim.x + threadIdx.x;
    if (i < NSLOT) {
        int e = g_topi[i];
        int p = atomicAdd(&g_cursor[e], 1);
        g_slot_token[p] = i >> 3;
        g_pos_of[i] = p;
    }
}

// ---------------- MoE gate+up, TF32 tensor cores, gathered A ----------------
// grid: (CF/64, E), 256 threads. Padded rows => no masking anywhere.
__global__ void moe_gateup_tf32(const float* __restrict__ w_gate,
                                const float* __restrict__ w_up) {
    int e = blockIdx.y;
    int n0 = blockIdx.x * 64;
    int off = g_offsets[e], cnt = g_counts[e];
    int ntiles = (cnt + 127) >> 7;
    const float* BG = w_gate + (size_t)e * CD * CF;
    const float* BU = w_up   + (size_t)e * CD * CF;
    __shared__ float As[128][36];
    __shared__ float BsG[32][68];
    __shared__ float BsU[32][68];
    __shared__ int stok[128];
    int tid = threadIdx.x;
    int w = tid >> 5;
    int wm = w & 3, wn = w >> 2;

    for (int rt = 0; rt < ntiles; rt++) {
        if (tid < 128) stok[tid] = g_slot_token[off + rt * 128 + tid];
        __syncthreads();
        FragC accG[2][2], accU[2][2];
#pragma unroll
        for (int i = 0; i < 2; i++)
#pragma unroll
            for (int j = 0; j < 2; j++) { wmma::fill_fragment(accG[i][j], 0.f); wmma::fill_fragment(accU[i][j], 0.f); }

        for (int k0 = 0; k0 < CD; k0 += 32) {
#pragma unroll
            for (int it = 0; it < 4; it++) {
                int i = tid + it * 256;
                int row = i >> 3, c4 = (i & 7) * 4;
                *(float4*)&As[row][c4] = *(const float4*)&g_ht[(size_t)stok[row] * CD + k0 + c4];
            }
#pragma unroll
            for (int it = 0; it < 2; it++) {
                int i = tid + it * 256;
                int row = i >> 4, c4 = (i & 15) * 4;
                *(float4*)&BsG[row][c4] = *(const float4*)&BG[(size_t)(k0 + row) * CF + n0 + c4];
                *(float4*)&BsU[row][c4] = *(const float4*)&BU[(size_t)(k0 + row) * CF + n0 + c4];
            }
            __syncthreads();
#pragma unroll
            for (int kk = 0; kk < 4; kk++) {
                FragA a[2]; FragB bg[2], bu[2];
#pragma unroll
                for (int i = 0; i < 2; i++) ld_a(a[i], &As[wm * 32 + i * 16][kk * 8], 36);
#pragma unroll
                for (int j = 0; j < 2; j++) {
                    ld_b(bg[j], &BsG[kk * 8][wn * 32 + j * 16], 68);
                    ld_b(bu[j], &BsU[kk * 8][wn * 32 + j * 16], 68);
                }
#pragma unroll
                for (int i = 0; i < 2; i++)
#pragma unroll
                    for (int j = 0; j < 2; j++) {
                        wmma::mma_sync(accG[i][j], a[i], bg[j], accG[i][j]);
                        wmma::mma_sync(accU[i][j], a[i], bu[j], accU[i][j]);
                    }
            }
            __syncthreads();
        }
        // silu(g)*u epilogue, direct store (padded rows are safe)
#pragma unroll
        for (int i = 0; i < 2; i++)
#pragma unroll
            for (int j = 0; j < 2; j++) {
#pragma unroll
                for (int e2 = 0; e2 < accG[i][j].num_elements; e2++) {
                    float g = accG[i][j].x[e2];
                    float u = accU[i][j].x[e2];
                    accG[i][j].x[e2] = (g / (1.f + expf(-g))) * u;
                }
                float* cp = g_act + (size_t)(off + rt * 128 + wm * 32 + i * 16) * CF + n0 + wn * 32 + j * 16;
                wmma::store_matrix_sync(cp, accG[i][j], CF, wmma::mem_row_major);
            }
        __syncthreads();
    }
}

// ---------------- MoE down, TF32, contiguous A ----------------
// grid: (CD/64, E), 256 threads
__global__ void moe_down_tf32(const float* __restrict__ w_down) {
    int e = blockIdx.y;
    int n0 = blockIdx.x * 64;
    int off = g_offsets[e], cnt = g_counts[e];
    int ntiles = (cnt + 127) >> 7;
    const float* Bm = w_down + (size_t)e * CF * CD;
    __shared__ float As[128][36];
    __shared__ float Bs[32][68];
    int tid = threadIdx.x;
    int w = tid >> 5;
    int wm = w & 3, wn = w >> 2;

    for (int rt = 0; rt < ntiles; rt++) {
        FragC acc[2][2];
#pragma unroll
        for (int i = 0; i < 2; i++)
#pragma unroll
            for (int j = 0; j < 2; j++) wmma::fill_fragment(acc[i][j], 0.f);

        for (int k0 = 0; k0 < CF; k0 += 32) {
#pragma unroll
            for (int it = 0; it < 4; it++) {
                int i = tid + it * 256;
                int row = i >> 3, c4 = (i & 7) * 4;
                *(float4*)&As[row][c4] =
                    *(const float4*)&g_act[(size_t)(off + rt * 128 + row) * CF + k0 + c4];
            }
#pragma unroll
            for (int it = 0; it < 2; it++) {
                int i = tid + it * 256;
                int row = i >> 4, c4 = (i & 15) * 4;
                *(float4*)&Bs[row][c4] = *(const float4*)&Bm[(size_t)(k0 + row) * CD + n0 + c4];
            }
            __syncthreads();
#pragma unroll
            for (int kk = 0; kk < 4; kk++) {
                FragA a[2]; FragB b[2];
#pragma unroll
                for (int i = 0; i < 2; i++) ld_a(a[i], &As[wm * 32 + i * 16][kk * 8], 36);
#pragma unroll
                for (int j = 0; j < 2; j++) ld_b(b[j], &Bs[kk * 8][wn * 32 + j * 16], 68);
#pragma unroll
                for (int i = 0; i < 2; i++)
#pragma unroll
                    for (int j = 0; j < 2; j++) wmma::mma_sync(acc[i][j], a[i], b[j], acc[i][j]);
            }
            __syncthreads();
        }
#pragma unroll
        for (int i = 0; i < 2; i++)
#pragma unroll
            for (int j = 0; j < 2; j++) {
                float* cp = g_y + (size_t)(off + rt * 128 + wm * 32 + i * 16) * CD + n0 + wn * 32 + j * 16;
                wmma::store_matrix_sync(cp, acc[i][j], CD, wmma::mem_row_major);
            }
    }
}

// ---------------- final combine ----------------
__global__ void final_add_kernel(float* __restrict__ out) {
    int t = blockIdx.x;
    __shared__ int   pos[8];
    __shared__ float w[8];
    if (threadIdx.x < 8) {
        pos[threadIdx.x] = g_pos_of[t * CK + threadIdx.x];
        w[threadIdx.x]   = g_topw[t * CK + threadIdx.x];
    }
    __syncthreads();
    for (int d = threadIdx.x; d < CD; d += 256) {
        float acc = out[(size_t)t * CD + d];
#pragma unroll
        for (int k = 0; k < 8; k++)
            acc += w[k] * g_y[(size_t)pos[k] * CD + d];
        out[(size_t)t * CD + d] = acc;
    }
}

// ---------------- launch ----------------
extern "C" void kernel_launch(void* const* d_in, const int* in_sizes, int n_in,
                              void* d_out, int out_size) {
    const float* x        = (const float*)d_in[0];
    const float* cos_     = (const float*)d_in[1];
    const float* sin_     = (const float*)d_in[2];
    const float* ln1_w    = (const float*)d_in[3];
    const float* wq       = (const float*)d_in[4];
    const float* wk       = (const float*)d_in[5];
    const float* wv       = (const float*)d_in[6];
    const float* wo       = (const float*)d_in[7];
    const float* qn_w     = (const float*)d_in[8];
    const float* kn_w     = (const float*)d_in[9];
    const float* ln2_w    = (const float*)d_in[10];
    const float* router_w = (const float*)d_in[11];
    const float* w_gate   = (const float*)d_in[12];
    const float* w_up     = (const float*)d_in[13];
    const float* w_down   = (const float*)d_in[14];
    float* out = (float*)d_out;

    float *p_h, *p_q, *p_k, *p_v, *p_o, *p_ht, *p_logits;
    cudaGetSymbolAddress((void**)&p_h,  g_h);
    cudaGetSymbolAddress((void**)&p_q,  g_q);
    cudaGetSymbolAddress((void**)&p_k,  g_k);
    cudaGetSymbolAddress((void**)&p_v,  g_v);
    cudaGetSymbolAddress((void**)&p_o,  g_o);
    cudaGetSymbolAddress((void**)&p_ht, g_ht);
    cudaGetSymbolAddress((void**)&p_logits, g_logits);

    // 1. h = rmsnorm(x)
    rmsnorm_kernel<<<CT, 256>>>(x, ln1_w, p_h);
    // 2. q,k,v projections (TF32 tensor cores)
    gemm_tf32<<<dim3((CH * CHD) / 64, CT / 128), 256>>>(p_h, wq, nullptr, p_q, CT, CH * CHD, CD);
    gemm_tf32<<<dim3((CKVH * CHD) / 64, CT / 128), 256>>>(p_h, wk, nullptr, p_k, CT, CKVH * CHD, CD);
    gemm_tf32<<<dim3((CKVH * CHD) / 64, CT / 128), 256>>>(p_h, wv, nullptr, p_v, CT, CKVH * CHD, CD);
    // 3. per-head q/k rmsnorm + rope
    qknorm_rope_kernel<<<dim3(CT, CH + CKVH), 128>>>(cos_, sin_, qn_w, kn_w);
    // 4. attention (exact fp32)
    attn_kernel<<<dim3(CS / 32, CH, CB), 128>>>();
    // 5. out = o @ wo + x
    gemm_tf32<<<dim3(CD / 64, CT / 128), 256>>>(p_o, wo, x, out, CT, CD, CD);
    // 6. ht = rmsnorm(out)
    rmsnorm_kernel<<<CT, 256>>>(out, ln2_w, p_ht);
    // 7. router logits (exact fp32 — feeds top-k selection) + top-8
    gemm64<<<dim3(CE / 64, CT / 64), 256>>>(p_ht, router_w, nullptr, p_logits, CT, CE, CD);
    topk_kernel<<<CT, 64>>>();
    // 8. routing bookkeeping with 128-row padding per expert
    zero_counts_kernel<<<1, 64>>>();
    count_kernel<<<NSLOT / 256, 256>>>();
    scan_kernel<<<1, 1>>>();
    init_slots_kernel<<<PADTOT / 256, 256>>>();
    fill_kernel<<<NSLOT / 256, 256>>>();
    // 9. expert gate/up + silu (TF32)
    moe_gateup_tf32<<<dim3(CF / 64, CE), 256>>>(w_gate, w_up);
    // 10. expert down (TF32)
    moe_down_tf32<<<dim3(CD / 64, CE), 256>>>(w_down);
    // 11. deterministic per-token combine
    final_add_kernel<<<CT, 256>>>(out);
}

// round 3
// speedup vs baseline: 1.5951x; 1.4949x over previous
#include <cuda_runtime.h>
#include <cuda_bf16.h>
#include <math.h>
#include <mma.h>
using namespace nvcuda;

// ---------------- problem constants ----------------
constexpr int CB  = 2;
constexpr int CS  = 1024;
constexpr int CD  = 2048;
constexpr int CH  = 16;
constexpr int CKVH= 4;
constexpr int CHD = 128;
constexpr int CE  = 64;
constexpr int CK  = 8;
constexpr int CF  = 768;
constexpr int CT  = CB * CS;             // 2048
constexpr float CEPS = 1e-6f;
constexpr int NSLOT = CT * CK;           // 16384
constexpr int PADTOT = NSLOT + CE * 128; // 24576

// ---------------- scratch ----------------
__device__ float g_h   [CT * CD];
__device__ float g_q   [CT * CH  * CHD];
__device__ float g_k   [CT * CKVH* CHD];
__device__ float g_v   [CT * CKVH* CHD];
__device__ float g_o   [CT * CH  * CHD];
__device__ float g_ht  [CT * CD];
__device__ __nv_bfloat16 g_ht_bf[CT * CD];
__device__ float g_logits[CT * CE];
__device__ int   g_topi[CT * CK];
__device__ float g_topw[CT * CK];
__device__ int   g_counts[CE];
__device__ int   g_offsets[CE];
__device__ int   g_cursor[CE];
__device__ int   g_slot_token[PADTOT];
__device__ int   g_pos_of[NSLOT];
__device__ __nv_bfloat16 g_act_bf[(size_t)PADTOT * CF];
__device__ float g_y   [(size_t)PADTOT * CD];

// ---------------- helpers ----------------
__device__ __forceinline__ void st_bf4(__nv_bfloat16* p, float4 v) {
    __nv_bfloat162 lo = __floats2bfloat162_rn(v.x, v.y);
    __nv_bfloat162 hi = __floats2bfloat162_rn(v.z, v.w);
    uint2 u;
    u.x = *(unsigned int*)&lo;
    u.y = *(unsigned int*)&hi;
    *(uint2*)p = u;
}

// ---------------- rmsnorm ----------------
__global__ void rmsnorm_kernel(const float* __restrict__ in,
                               const float* __restrict__ w,
                               float* __restrict__ out) {
    int t = blockIdx.x;
    const float* row = in + (size_t)t * CD;
    float ss = 0.f;
    for (int d = threadIdx.x; d < CD; d += 256) { float v = row[d]; ss += v * v; }
    __shared__ float red[256];
    red[threadIdx.x] = ss; __syncthreads();
    for (int st = 128; st > 0; st >>= 1) {
        if (threadIdx.x < st) red[threadIdx.x] += red[threadIdx.x + st];
        __syncthreads();
    }
    float scale = rsqrtf(red[0] / (float)CD + CEPS);
    for (int d = threadIdx.x; d < CD; d += 256)
        out[(size_t)t * CD + d] = row[d] * scale * w[d];
}

// rmsnorm writing fp32 + bf16 copies (for MoE A-operand)
__global__ void rmsnorm_bf_kernel(const float* __restrict__ in,
                                  const float* __restrict__ w,
                                  float* __restrict__ out,
                                  __nv_bfloat16* __restrict__ outb) {
    int t = blockIdx.x;
    const float* row = in + (size_t)t * CD;
    float ss = 0.f;
    for (int d = threadIdx.x; d < CD; d += 256) { float v = row[d]; ss += v * v; }
    __shared__ float red[256];
    red[threadIdx.x] = ss; __syncthreads();
    for (int st = 128; st > 0; st >>= 1) {
        if (threadIdx.x < st) red[threadIdx.x] += red[threadIdx.x + st];
        __syncthreads();
    }
    float scale = rsqrtf(red[0] / (float)CD + CEPS);
    for (int d = threadIdx.x; d < CD; d += 256) {
        float v = row[d] * scale * w[d];
        out[(size_t)t * CD + d] = v;
        outb[(size_t)t * CD + d] = __float2bfloat16(v);
    }
}

// ---------------- scalar GEMM (router: exact fp32 feeds top-k) -------
__global__ void gemm64(const float* __restrict__ A, const float* __restrict__ Bm,
                       const float* __restrict__ res, float* __restrict__ C,
                       int M, int N, int K) {
    __shared__ float As[16][65];
    __shared__ float Bs[16][64];
    int tid = threadIdx.x;
    int tx = tid & 15, ty = tid >> 4;
    int m0 = blockIdx.y * 64, n0 = blockIdx.x * 64;
    int arow = tid >> 2;
    int acol = (tid & 3) * 4;
    int blin = tid * 4;
    int brow = blin >> 6;
    int bcol = blin & 63;
    const float* Aptr = A + (size_t)(m0 + arow) * K + acol;
    const float* Bptr = Bm + (size_t)brow * N + n0 + bcol;
    float acc[4][4] = {};
    for (int k0 = 0; k0 < K; k0 += 16) {
        float4 av = *(const float4*)(Aptr + k0);
        float4 bv = *(const float4*)(Bptr + (size_t)k0 * N);
        As[acol + 0][arow] = av.x; As[acol + 1][arow] = av.y;
        As[acol + 2][arow] = av.z; As[acol + 3][arow] = av.w;
        *(float4*)&Bs[brow][bcol] = bv;
        __syncthreads();
#pragma unroll
        for (int kk = 0; kk < 16; kk++) {
            float a[4], b[4];
#pragma unroll
            for (int i = 0; i < 4; i++) a[i] = As[kk][ty * 4 + i];
#pragma unroll
            for (int j = 0; j < 4; j++) b[j] = Bs[kk][tx * 4 + j];
#pragma unroll
            for (int i = 0; i < 4; i++)
#pragma unroll
                for (int j = 0; j < 4; j++) acc[i][j] += a[i] * b[j];
        }
        __syncthreads();
    }
#pragma unroll
    for (int i = 0; i < 4; i++)
#pragma unroll
        for (int j = 0; j < 4; j++) {
            size_t idx = (size_t)(m0 + ty * 4 + i) * N + n0 + tx * 4 + j;
            C[idx] = acc[i][j] + (res ? res[idx] : 0.f);
        }
}

// ---------------- fragment types ----------------
using FragAT = wmma::fragment<wmma::matrix_a, 16, 16, 8, wmma::precision::tf32, wmma::row_major>;
using FragBT = wmma::fragment<wmma::matrix_b, 16, 16, 8, wmma::precision::tf32, wmma::row_major>;
using FragAB = wmma::fragment<wmma::matrix_a, 16, 16, 16, __nv_bfloat16, wmma::row_major>;
using FragBB = wmma::fragment<wmma::matrix_b, 16, 16, 16, __nv_bfloat16, wmma::row_major>;
using FragC  = wmma::fragment<wmma::accumulator, 16, 16, 8, float>;
using FragCB = wmma::fragment<wmma::accumulator, 16, 16, 16, float>;

__device__ __forceinline__ void ld_at(FragAT& f, const float* p, int ld) {
    wmma::load_matrix_sync(f, p, ld);
#pragma unroll
    for (int i = 0; i < f.num_elements; i++) f.x[i] = wmma::__float_to_tf32(f.x[i]);
}
__device__ __forceinline__ void ld_bt(FragBT& f, const float* p, int ld) {
    wmma::load_matrix_sync(f, p, ld);
#pragma unroll
    for (int i = 0; i < f.num_elements; i++) f.x[i] = wmma::__float_to_tf32(f.x[i]);
}

// ================= pipelined TF32 dense GEMM =================
// C[M,N] = A@B (+res). BM=128 BN=64 BK=32, 256 threads, double-buffered smem.
// dyn smem: As[2][128][36] f32 (36864 B) + Bs[2][32][68] f32 (17408 B) = 54272 B
constexpr int SM_TF32 = 2*128*36*4 + 2*32*68*4;

__global__ void gemm_tf32_pipe(const float* __restrict__ A, const float* __restrict__ B,
                               const float* __restrict__ res, float* __restrict__ C,
                               int M, int N, int K) {
    extern __shared__ char smraw[];
    float (*As)[128][36] = (float(*)[128][36])smraw;
    float (*Bs)[32][68]  = (float(*)[32][68])(smraw + 2*128*36*4);
    int tid = threadIdx.x;
    int w = tid >> 5, wm = w & 3, wn = w >> 2;
    int m0 = blockIdx.y * 128, n0 = blockIdx.x * 64;

    int a_row = tid >> 3, a_c4 = (tid & 7) * 4;       // +64 rows per it
    int b_row = tid >> 4, b_c4 = (tid & 15) * 4;      // +16 rows per it

    FragC acc[2][2];
#pragma unroll
    for (int i = 0; i < 2; i++)
#pragma unroll
        for (int j = 0; j < 2; j++) wmma::fill_fragment(acc[i][j], 0.f);

    float4 ra[4], rb[2];
    int nk = K / 32;
    // prologue: load k0=0
#pragma unroll
    for (int it = 0; it < 4; it++)
        ra[it] = *(const float4*)&A[(size_t)(m0 + a_row + it * 32) * K + a_c4];
#pragma unroll
    for (int it = 0; it < 2; it++)
        rb[it] = *(const float4*)&B[(size_t)(b_row + it * 16) * N + n0 + b_c4];
#pragma unroll
    for (int it = 0; it < 4; it++) *(float4*)&As[0][a_row + it * 32][a_c4] = ra[it];
#pragma unroll
    for (int it = 0; it < 2; it++) *(float4*)&Bs[0][b_row + it * 16][b_c4] = rb[it];
    __syncthreads();

    for (int k = 0; k < nk; k++) {
        int cur = k & 1;
        if (k + 1 < nk) {
            int k0 = (k + 1) * 32;
#pragma unroll
            for (int it = 0; it < 4; it++)
                ra[it] = *(const float4*)&A[(size_t)(m0 + a_row + it * 32) * K + k0 + a_c4];
#pragma unroll
            for (int it = 0; it < 2; it++)
                rb[it] = *(const float4*)&B[(size_t)(k0 + b_row + it * 16) * N + n0 + b_c4];
        }
#pragma unroll
        for (int kk = 0; kk < 4; kk++) {
            FragAT a[2]; FragBT b[2];
#pragma unroll
            for (int i = 0; i < 2; i++) ld_at(a[i], &As[cur][wm * 32 + i * 16][kk * 8], 36);
#pragma unroll
            for (int j = 0; j < 2; j++) ld_bt(b[j], &Bs[cur][kk * 8][wn * 32 + j * 16], 68);
#pragma unroll
            for (int i = 0; i < 2; i++)
#pragma unroll
                for (int j = 0; j < 2; j++) wmma::mma_sync(acc[i][j], a[i], b[j], acc[i][j]);
        }
        if (k + 1 < nk) {
            int nxt = cur ^ 1;
#pragma unroll
            for (int it = 0; it < 4; it++) *(float4*)&As[nxt][a_row + it * 32][a_c4] = ra[it];
#pragma unroll
            for (int it = 0; it < 2; it++) *(float4*)&Bs[nxt][b_row + it * 16][b_c4] = rb[it];
        }
        __syncthreads();
    }
#pragma unroll
    for (int i = 0; i < 2; i++)
#pragma unroll
        for (int j = 0; j < 2; j++) {
            size_t co = (size_t)(m0 + wm * 32 + i * 16) * N + n0 + wn * 32 + j * 16;
            if (res) {
                FragC r;
                wmma::load_matrix_sync(r, res + co, N, wmma::mem_row_major);
#pragma unroll
                for (int e2 = 0; e2 < r.num_elements; e2++) acc[i][j].x[e2] += r.x[e2];
            }
            wmma::store_matrix_sync(C + co, acc[i][j], N, wmma::mem_row_major);
        }
}

// ---------------- per-head q/k rmsnorm + rope ----------------
__global__ void qknorm_rope_kernel(const float* __restrict__ cos_,
                                   const float* __restrict__ sin_,
                                   const float* __restrict__ qn_w,
                                   const float* __restrict__ kn_w) {
    int t = blockIdx.x;
    int hy = blockIdx.y;
    int d = threadIdx.x;
    float* ptr; const float* w;
    if (hy < CH) { ptr = g_q + ((size_t)t * CH + hy) * CHD;          w = qn_w; }
    else         { ptr = g_k + ((size_t)t * CKVH + (hy - CH)) * CHD; w = kn_w; }
    float v = ptr[d];
    float ss = v * v;
#pragma unroll
    for (int off = 16; off > 0; off >>= 1) ss += __shfl_xor_sync(0xffffffffu, ss, off);
    __shared__ float ws[4];
    if ((d & 31) == 0) ws[d >> 5] = ss;
    __syncthreads();
    float tot = ws[0] + ws[1] + ws[2] + ws[3];
    float nrm = v * rsqrtf(tot / (float)CHD + CEPS) * w[d];
    __shared__ float nbuf[128];
    nbuf[d] = nrm;
    __syncthreads();
    float rot = (d < 64) ? -nbuf[d + 64] : nbuf[d - 64];
    float c = cos_[(size_t)t * CHD + d];
    float s = sin_[(size_t)t * CHD + d];
    ptr[d] = nrm * c + rot * s;
}

// ---------------- flash attention (causal, GQA), exact fp32 ----------------
__global__ void attn_kernel() {
    int qt = blockIdx.x;
    int h  = blockIdx.y;
    int b  = blockIdx.z;
    int kvh = h / (CH / CKVH);
    int tid = threadIdx.x;
    int r  = tid >> 2;
    int qd = tid & 3;
    __shared__ float Qs[32][128];
    __shared__ float KVs[32][128];
    __shared__ float Ss[32][33];

    for (int i = tid; i < 32 * 128; i += 128) {
        int rr = i >> 7, dd = i & 127;
        Qs[rr][dd] = g_q[((size_t)(b * CS + qt * 32 + rr) * CH + h) * CHD + dd];
    }
    float acc[32];
#pragma unroll
    for (int i = 0; i < 32; i++) acc[i] = 0.f;
    float m = -1e30f, l = 0.f;
    const float scale = 0.088388347648318447f;

    for (int jt = 0; jt <= qt; jt++) {
        __syncthreads();
        for (int i = tid; i < 32 * 128; i += 128) {
            int rr = i >> 7, dd = i & 127;
            KVs[rr][dd] = g_k[((size_t)(b * CS + jt * 32 + rr) * CKVH + kvh) * CHD + dd];
        }
        __syncthreads();
        float sc[8];
#pragma unroll
        for (int jj = 0; jj < 8; jj++) sc[jj] = 0.f;
        for (int dd = 0; dd < 128; dd++) {
            float qv = Qs[r][dd];
#pragma unroll
            for (int jj = 0; jj < 8; jj++) sc[jj] += qv * KVs[qd * 8 + jj][dd];
        }
        int qg = qt * 32 + r;
#pragma unroll
        for (int jj = 0; jj < 8; jj++) {
            int kg = jt * 32 + qd * 8 + jj;
            float v = sc[jj] * scale;
            if (kg > qg) v = -1e30f;
            Ss[r][qd * 8 + jj] = v;
        }
        __syncthreads();
        float tm = m;
#pragma unroll
        for (int c = 0; c < 32; c++) tm = fmaxf(tm, Ss[r][c]);
        float alpha = expf(m - tm);
        float p[32];
        float lsum = 0.f;
#pragma unroll
        for (int c = 0; c < 32; c++) { p[c] = expf(Ss[r][c] - tm); lsum += p[c]; }
        l = l * alpha + lsum;
        m = tm;
        __syncthreads();
        for (int i = tid; i < 32 * 128; i += 128) {
            int rr = i >> 7, dd = i & 127;
            KVs[rr][dd] = g_v[((size_t)(b * CS + jt * 32 + rr) * CKVH + kvh) * CHD + dd];
        }
        __syncthreads();
#pragma unroll
        for (int dd = 0; dd < 32; dd++) acc[dd] *= alpha;
        for (int c = 0; c < 32; c++) {
            float pv = p[c];
#pragma unroll
            for (int dd = 0; dd < 32; dd++) acc[dd] += pv * KVs[c][qd * 32 + dd];
        }
    }
    float inv = 1.f / l;
    int t = b * CS + qt * 32 + r;
#pragma unroll
    for (int dd = 0; dd < 32; dd++)
        g_o[((size_t)t * CH + h) * CHD + qd * 32 + dd] = acc[dd] * inv;
}

// ---------------- router softmax + top-8 ----------------
__global__ void topk_kernel() {
    int t = blockIdx.x, e = threadIdx.x;
    __shared__ float red[64];
    __shared__ int   redi[64];
    __shared__ float tv[8];
    __shared__ int   ti[8];
    float lg = g_logits[t * CE + e];
    red[e] = lg; __syncthreads();
    for (int st = 32; st > 0; st >>= 1) {
        if (e < st) red[e] = fmaxf(red[e], red[e + st]);
        __syncthreads();
    }
    float mx = red[0]; __syncthreads();
    float ex = expf(lg - mx);
    red[e] = ex; __syncthreads();
    for (int st = 32; st > 0; st >>= 1) {
        if (e < st) red[e] += red[e + st];
        __syncthreads();
    }
    float sum = red[0]; __syncthreads();
    float sel = ex / sum;
    for (int k = 0; k < 8; k++) {
        red[e] = sel; redi[e] = e; __syncthreads();
        for (int st = 32; st > 0; st >>= 1) {
            if (e < st) {
                if (red[e + st] > red[e]) { red[e] = red[e + st]; redi[e] = redi[e + st]; }
            }
            __syncthreads();
        }
        if (e == 0) { tv[k] = red[0]; ti[k] = redi[0]; }
        __syncthreads();
        if (e == ti[k]) sel = -1.f;
        __syncthreads();
    }
    if (e < 8) {
        float s8 = 0.f;
#pragma unroll
        for (int k = 0; k < 8; k++) s8 += tv[k];
        g_topi[t * CK + e] = ti[e];
        g_topw[t * CK + e] = tv[e] / s8;
    }
}

// ---------------- routing bookkeeping ----------------
__global__ void zero_counts_kernel() { if (threadIdx.x < CE) g_counts[threadIdx.x] = 0; }

__global__ void count_kernel() {
    int i = blockIdx.x * blockDim.x + threadIdx.x;
    if (i < NSLOT) atomicAdd(&g_counts[g_topi[i]], 1);
}

__global__ void scan_kernel() {
    int acc = 0;
    for (int e = 0; e < CE; e++) {
        g_offsets[e] = acc;
        g_cursor[e]  = acc;
        acc += ((g_counts[e] + 127) >> 7) << 7;
    }
}

__global__ void init_slots_kernel() {
    int i = blockIdx.x * blockDim.x + threadIdx.x;
    if (i < PADTOT) g_slot_token[i] = 0;
}

__global__ void fill_kernel() {
    int i = blockIdx.x * blockDim.x + threadIdx.x;
    if (i < NSLOT) {
        int e = g_topi[i];
        int p = atomicAdd(&g_cursor[e], 1);
        g_slot_token[p] = i >> 3;
        g_pos_of[i] = p;
    }
}

// ================= MoE gate+up, BF16 pipelined =================
// dyn smem layout (bytes):
//   As  bf16[2][128][40]  @0      (20480)
//   BsG bf16[2][32][72]   @20480  (9216)
//   BsU bf16[2][32][72]   @29696  (9216)
//   stok int[128]         @38912  (512)
//   scr  float[8][16][16] @39424  (8192)   total 47616
constexpr int SM_GATEUP = 47616;

__global__ void moe_gateup_bf16(const float* __restrict__ w_gate,
                                const float* __restrict__ w_up) {
    extern __shared__ char smraw[];
    __nv_bfloat16 (*As)[128][40] = (__nv_bfloat16(*)[128][40])smraw;
    __nv_bfloat16 (*BsG)[32][72] = (__nv_bfloat16(*)[32][72])(smraw + 20480);
    __nv_bfloat16 (*BsU)[32][72] = (__nv_bfloat16(*)[32][72])(smraw + 29696);
    int* stok = (int*)(smraw + 38912);
    float (*scr)[16][16] = (float(*)[16][16])(smraw + 39424);

    int e = blockIdx.y;
    int n0 = blockIdx.x * 64;
    int off = g_offsets[e], cnt = g_counts[e];
    int ntiles = (cnt + 127) >> 7;
    const float* BG = w_gate + (size_t)e * CD * CF;
    const float* BU = w_up   + (size_t)e * CD * CF;

    int tid = threadIdx.x;
    int w = tid >> 5, wm = w & 3, wn = w >> 2;
    int lane = tid & 31;

    int a_row = tid >> 1, a_c8 = (tid & 1) * 8;       // +64 rows per it? no:
    // A stage: 128 rows x 32 bf16 cols = 4096 elems = 256thr x 16 = 2 x uint4(8 elems)
    // i = tid + it*256: row = i>>2, c8 = (i&3)*8
    int b_row = tid >> 4, b_c4 = (tid & 15) * 4;      // B: 32x64 per it covers 16 rows

    for (int rt = 0; rt < ntiles; rt++) {
        if (tid < 128) stok[tid] = g_slot_token[off + rt * 128 + tid];
        __syncthreads();

        FragCB accG[2][2], accU[2][2];
#pragma unroll
        for (int i = 0; i < 2; i++)
#pragma unroll
            for (int j = 0; j < 2; j++) { wmma::fill_fragment(accG[i][j], 0.f); wmma::fill_fragment(accU[i][j], 0.f); }

        uint4 raA[2]; float4 rbg[2], rbu[2];
        int nk = CD / 32;
        // prologue
#pragma unroll
        for (int it = 0; it < 2; it++) {
            int i = tid + it * 256;
            int row = i >> 2, c8 = (i & 3) * 8;
            raA[it] = *(const uint4*)&g_ht_bf[(size_t)stok[row] * CD + c8];
        }
#pragma unroll
        for (int it = 0; it < 2; it++) {
            int row = b_row + it * 16;
            rbg[it] = *(const float4*)&BG[(size_t)row * CF + n0 + b_c4];
            rbu[it] = *(const float4*)&BU[(size_t)row * CF + n0 + b_c4];
        }
#pragma unroll
        for (int it = 0; it < 2; it++) {
            int i = tid + it * 256;
            int row = i >> 2, c8 = (i & 3) * 8;
            *(uint4*)&As[0][row][c8] = raA[it];
        }
#pragma unroll
        for (int it = 0; it < 2; it++) {
            int row = b_row + it * 16;
            st_bf4(&BsG[0][row][b_c4], rbg[it]);
            st_bf4(&BsU[0][row][b_c4], rbu[it]);
        }
        __syncthreads();

        for (int k = 0; k < nk; k++) {
            int cur = k & 1;
            if (k + 1 < nk) {
                int k0 = (k + 1) * 32;
#pragma unroll
                for (int it = 0; it < 2; it++) {
                    int i = tid + it * 256;
                    int row = i >> 2, c8 = (i & 3) * 8;
                    raA[it] = *(const uint4*)&g_ht_bf[(size_t)stok[row] * CD + k0 + c8];
                }
#pragma unroll
                for (int it = 0; it < 2; it++) {
                    int row = b_row + it * 16;
                    rbg[it] = *(const float4*)&BG[(size_t)(k0 + row) * CF + n0 + b_c4];
                    rbu[it] = *(const float4*)&BU[(size_t)(k0 + row) * CF + n0 + b_c4];
                }
            }
#pragma unroll
            for (int kk = 0; kk < 2; kk++) {
                FragAB a[2]; FragBB bg[2], bu[2];
#pragma unroll
                for (int i = 0; i < 2; i++)
                    wmma::load_matrix_sync(a[i], &As[cur][wm * 32 + i * 16][kk * 16], 40);
#pragma unroll
                for (int j = 0; j < 2; j++) {
                    wmma::load_matrix_sync(bg[j], &BsG[cur][kk * 16][wn * 32 + j * 16], 72);
                    wmma::load_matrix_sync(bu[j], &BsU[cur][kk * 16][wn * 32 + j * 16], 72);
                }
#pragma unroll
                for (int i = 0; i < 2; i++)
#pragma unroll
                    for (int j = 0; j < 2; j++) {
                        wmma::mma_sync(accG[i][j], a[i], bg[j], accG[i][j]);
                        wmma::mma_sync(accU[i][j], a[i], bu[j], accU[i][j]);
                    }
            }
            if (k + 1 < nk) {
                int nxt = cur ^ 1;
#pragma unroll
                for (int it = 0; it < 2; it++) {
                    int i = tid + it * 256;
                    int row = i >> 2, c8 = (i & 3) * 8;
                    *(uint4*)&As[nxt][row][c8] = raA[it];
                }
#pragma unroll
                for (int it = 0; it < 2; it++) {
                    int row = b_row + it * 16;
                    st_bf4(&BsG[nxt][row][b_c4], rbg[it]);
                    st_bf4(&BsU[nxt][row][b_c4], rbu[it]);
                }
            }
            __syncthreads();
        }

        // epilogue: silu(g)*u -> bf16, via per-warp smem scratch
#pragma unroll
        for (int i = 0; i < 2; i++)
#pragma unroll
            for (int j = 0; j < 2; j++) {
#pragma unroll
                for (int e2 = 0; e2 < accG[i][j].num_elements; e2++) {
                    float g = accG[i][j].x[e2];
                    float u = accU[i][j].x[e2];
                    accG[i][j].x[e2] = (g / (1.f + expf(-g))) * u;
                }
                wmma::store_matrix_sync(&scr[w][0][0], accG[i][j], 16, wmma::mem_row_major);
                __syncwarp();
                {
                    int r = lane >> 1, cb = (lane & 1) * 8;
                    float4 lo = *(float4*)&scr[w][r][cb];
                    float4 hi = *(float4*)&scr[w][r][cb + 4];
                    size_t grow = (size_t)(off + rt * 128 + wm * 32 + i * 16 + r);
                    __nv_bfloat16* dst = g_act_bf + grow * CF + n0 + wn * 32 + j * 16 + cb;
                    st_bf4(dst, lo);
                    st_bf4(dst + 4, hi);
                }
                __syncwarp();
            }
        __syncthreads();
    }
}

// ================= MoE down, BF16 pipelined =================
// dyn smem: As bf16[2][128][40] @0 (20480) + Bs bf16[2][32][72] @20480 (9216) = 29696
constexpr int SM_DOWN = 29696;

__global__ void moe_down_bf16(const float* __restrict__ w_down) {
    extern __shared__ char smraw[];
    __nv_bfloat16 (*As)[128][40] = (__nv_bfloat16(*)[128][40])smraw;
    __nv_bfloat16 (*Bs)[32][72]  = (__nv_bfloat16(*)[32][72])(smraw + 20480);

    int e = blockIdx.y;
    int n0 = blockIdx.x * 64;
    int off = g_offsets[e], cnt = g_counts[e];
    int ntiles = (cnt + 127) >> 7;
    const float* Bm = w_down + (size_t)e * CF * CD;

    int tid = threadIdx.x;
    int w = tid >> 5, wm = w & 3, wn = w >> 2;
    int b_row = tid >> 4, b_c4 = (tid & 15) * 4;

    for (int rt = 0; rt < ntiles; rt++) {
        FragCB acc[2][2];
#pragma unroll
        for (int i = 0; i < 2; i++)
#pragma unroll
            for (int j = 0; j < 2; j++) wmma::fill_fragment(acc[i][j], 0.f);

        uint4 raA[2]; float4 rb[2];
        int nk = CF / 32;
        size_t abase = (size_t)(off + rt * 128);
        // prologue
#pragma unroll
        for (int it = 0; it < 2; it++) {
            int i = tid + it * 256;
            int row = i >> 2, c8 = (i & 3) * 8;
            raA[it] = *(const uint4*)&g_act_bf[(abase + row) * CF + c8];
        }
#pragma unroll
        for (int it = 0; it < 2; it++) {
            int row = b_row + it * 16;
            rb[it] = *(const float4*)&Bm[(size_t)row * CD + n0 + b_c4];
        }
#pragma unroll
        for (int it = 0; it < 2; it++) {
            int i = tid + it * 256;
            int row = i >> 2, c8 = (i & 3) * 8;
            *(uint4*)&As[0][row][c8] = raA[it];
        }
#pragma unroll
        for (int it = 0; it < 2; it++)
            st_bf4(&Bs[0][b_row + it * 16][b_c4], rb[it]);
        __syncthreads();

        for (int k = 0; k < nk; k++) {
            int cur = k & 1;
            if (k + 1 < nk) {
                int k0 = (k + 1) * 32;
#pragma unroll
                for (int it = 0; it < 2; it++) {
                    int i = tid + it * 256;
                    int row = i >> 2, c8 = (i & 3) * 8;
                    raA[it] = *(const uint4*)&g_act_bf[(abase + row) * CF + k0 + c8];
                }
#pragma unroll
                for (int it = 0; it < 2; it++) {
                    int row = b_row + it * 16;
                    rb[it] = *(const float4*)&Bm[(size_t)(k0 + row) * CD + n0 + b_c4];
                }
            }
#pragma unroll
            for (int kk = 0; kk < 2; kk++) {
                FragAB a[2]; FragBB b[2];
#pragma unroll
                for (int i = 0; i < 2; i++)
                    wmma::load_matrix_sync(a[i], &As[cur][wm * 32 + i * 16][kk * 16], 40);
#pragma unroll
                for (int j = 0; j < 2; j++)
                    wmma::load_matrix_sync(b[j], &Bs[cur][kk * 16][wn * 32 + j * 16], 72);
#pragma unroll
                for (int i = 0; i < 2; i++)
#pragma unroll
                    for (int j = 0; j < 2; j++) wmma::mma_sync(acc[i][j], a[i], b[j], acc[i][j]);
            }
            if (k + 1 < nk) {
                int nxt = cur ^ 1;
#pragma unroll
                for (int it = 0; it < 2; it++) {
                    int i = tid + it * 256;
                    int row = i >> 2, c8 = (i & 3) * 8;
                    *(uint4*)&As[nxt][row][c8] = raA[it];
                }
#pragma unroll
                for (int it = 0; it < 2; it++)
                    st_bf4(&Bs[nxt][b_row + it * 16][b_c4], rb[it]);
            }
            __syncthreads();
        }
#pragma unroll
        for (int i = 0; i < 2; i++)
#pragma unroll
            for (int j = 0; j < 2; j++) {
                float* cp = g_y + (abase + wm * 32 + i * 16) * CD + n0 + wn * 32 + j * 16;
                wmma::store_matrix_sync(cp, acc[i][j], CD, wmma::mem_row_major);
            }
        __syncthreads();
    }
}

// ---------------- final combine ----------------
__global__ void final_add_kernel(float* __restrict__ out) {
    int t = blockIdx.x;
    __shared__ int   pos[8];
    __shared__ float w[8];
    if (threadIdx.x < 8) {
        pos[threadIdx.x] = g_pos_of[t * CK + threadIdx.x];
        w[threadIdx.x]   = g_topw[t * CK + threadIdx.x];
    }
    __syncthreads();
    for (int d = threadIdx.x; d < CD; d += 256) {
        float acc = out[(size_t)t * CD + d];
#pragma unroll
        for (int k = 0; k < 8; k++)
            acc += w[k] * g_y[(size_t)pos[k] * CD + d];
        out[(size_t)t * CD + d] = acc;
    }
}

// ---------------- launch ----------------
extern "C" void kernel_launch(void* const* d_in, const int* in_sizes, int n_in,
                              void* d_out, int out_size) {
    const float* x        = (const float*)d_in[0];
    const float* cos_     = (const float*)d_in[1];
    const float* sin_     = (const float*)d_in[2];
    const float* ln1_w    = (const float*)d_in[3];
    const float* wq       = (const float*)d_in[4];
    const float* wk       = (const float*)d_in[5];
    const float* wv       = (const float*)d_in[6];
    const float* wo       = (const float*)d_in[7];
    const float* qn_w     = (const float*)d_in[8];
    const float* kn_w     = (const float*)d_in[9];
    const float* ln2_w    = (const float*)d_in[10];
    const float* router_w = (const float*)d_in[11];
    const float* w_gate   = (const float*)d_in[12];
    const float* w_up     = (const float*)d_in[13];
    const float* w_down   = (const float*)d_in[14];
    float* out = (float*)d_out;

    static bool attr_done = false;
    if (!attr_done) {
        cudaFuncSetAttribute(gemm_tf32_pipe,  cudaFuncAttributeMaxDynamicSharedMemorySize, SM_TF32);
        cudaFuncSetAttribute(moe_gateup_bf16, cudaFuncAttributeMaxDynamicSharedMemorySize, SM_GATEUP);
        cudaFuncSetAttribute(moe_down_bf16,   cudaFuncAttributeMaxDynamicSharedMemorySize, SM_DOWN);
        attr_done = true;
    }

    float *p_h, *p_q, *p_k, *p_v, *p_o, *p_ht, *p_logits;
    __nv_bfloat16 *p_ht_bf;
    cudaGetSymbolAddress((void**)&p_h,  g_h);
    cudaGetSymbolAddress((void**)&p_q,  g_q);
    cudaGetSymbolAddress((void**)&p_k,  g_k);
    cudaGetSymbolAddress((void**)&p_v,  g_v);
    cudaGetSymbolAddress((void**)&p_o,  g_o);
    cudaGetSymbolAddress((void**)&p_ht, g_ht);
    cudaGetSymbolAddress((void**)&p_ht_bf, g_ht_bf);
    cudaGetSymbolAddress((void**)&p_logits, g_logits);

    // 1. h = rmsnorm(x)
    rmsnorm_kernel<<<CT, 256>>>(x, ln1_w, p_h);
    // 2. q,k,v projections (pipelined TF32)
    gemm_tf32_pipe<<<dim3((CH * CHD) / 64, CT / 128), 256, SM_TF32>>>(p_h, wq, nullptr, p_q, CT, CH * CHD, CD);
    gemm_tf32_pipe<<<dim3((CKVH * CHD) / 64, CT / 128), 256, SM_TF32>>>(p_h, wk, nullptr, p_k, CT, CKVH * CHD, CD);
    gemm_tf32_pipe<<<dim3((CKVH * CHD) / 64, CT / 128), 256, SM_TF32>>>(p_h, wv, nullptr, p_v, CT, CKVH * CHD, CD);
    // 3. per-head q/k rmsnorm + rope
    qknorm_rope_kernel<<<dim3(CT, CH + CKVH), 128>>>(cos_, sin_, qn_w, kn_w);
    // 4. attention (exact fp32)
    attn_kernel<<<dim3(CS / 32, CH, CB), 128>>>();
    // 5. out = o @ wo + x
    gemm_tf32_pipe<<<dim3(CD / 64, CT / 128), 256, SM_TF32>>>(p_o, wo, x, out, CT, CD, CD);
    // 6. ht = rmsnorm(out), fp32 + bf16
    rmsnorm_bf_kernel<<<CT, 256>>>(out, ln2_w, p_ht, p_ht_bf);
    // 7. router logits (exact fp32) + top-8
    gemm64<<<dim3(CE / 64, CT / 64), 256>>>(p_ht, router_w, nullptr, p_logits, CT, CE, CD);
    topk_kernel<<<CT, 64>>>();
    // 8. routing bookkeeping
    zero_counts_kernel<<<1, 64>>>();
    count_kernel<<<NSLOT / 256, 256>>>();
    scan_kernel<<<1, 1>>>();
    init_slots_kernel<<<PADTOT / 256, 256>>>();
    fill_kernel<<<NSLOT / 256, 256>>>();
    // 9. expert gate/up + silu (BF16 pipelined)
    moe_gateup_bf16<<<dim3(CF / 64, CE), 256, SM_GATEUP>>>(w_gate, w_up);
    // 10. expert down (BF16 pipelined)
    moe_down_bf16<<<dim3(CD / 64, CE), 256, SM_DOWN>>>(w_down);
    // 11. deterministic per-token combine
    final_add_kernel<<<CT, 256>>>(out);
}

// round 4
// speedup vs baseline: 1.6961x; 1.0633x over previous
#include <cuda_runtime.h>
#include <cuda_bf16.h>
#include <math.h>
#include <mma.h>
using namespace nvcuda;

// ---------------- problem constants ----------------
constexpr int CB  = 2;
constexpr int CS  = 1024;
constexpr int CD  = 2048;
constexpr int CH  = 16;
constexpr int CKVH= 4;
constexpr int CHD = 128;
constexpr int CE  = 64;
constexpr int CK  = 8;
constexpr int CF  = 768;
constexpr int CT  = CB * CS;             // 2048
constexpr float CEPS = 1e-6f;
constexpr int NSLOT = CT * CK;           // 16384
constexpr int PADTOT = NSLOT + CE * 128; // 24576

// ---------------- scratch ----------------
__device__ float g_h   [CT * CD];
__device__ float g_q   [CT * CH  * CHD];
__device__ float g_k   [CT * CKVH* CHD];
__device__ float g_v   [CT * CKVH* CHD];
__device__ float g_o   [CT * CH  * CHD];
__device__ float g_ht  [CT * CD];
__device__ __nv_bfloat16 g_ht_bf[CT * CD];
__device__ float g_logits[CT * CE];
__device__ int   g_topi[CT * CK];
__device__ float g_topw[CT * CK];
__device__ int   g_counts[CE];
__device__ int   g_offsets[CE];
__device__ int   g_cursor[CE];
__device__ int   g_slot_token[PADTOT];
__device__ int   g_pos_of[NSLOT];
__device__ float g_gate[(size_t)PADTOT * CF];     // gate GEMM raw output
__device__ __nv_bfloat16 g_act_bf[(size_t)PADTOT * CF];
__device__ float g_y   [(size_t)PADTOT * CD];

// ---------------- helpers ----------------
__device__ __forceinline__ void st_bf4(__nv_bfloat16* p, float4 v) {
    __nv_bfloat162 lo = __floats2bfloat162_rn(v.x, v.y);
    __nv_bfloat162 hi = __floats2bfloat162_rn(v.z, v.w);
    uint2 u;
    u.x = *(unsigned int*)&lo;
    u.y = *(unsigned int*)&hi;
    *(uint2*)p = u;
}

// ---------------- rmsnorm ----------------
__global__ void rmsnorm_kernel(const float* __restrict__ in,
                               const float* __restrict__ w,
                               float* __restrict__ out) {
    int t = blockIdx.x;
    const float* row = in + (size_t)t * CD;
    float ss = 0.f;
    for (int d = threadIdx.x; d < CD; d += 256) { float v = row[d]; ss += v * v; }
    __shared__ float red[256];
    red[threadIdx.x] = ss; __syncthreads();
    for (int st = 128; st > 0; st >>= 1) {
        if (threadIdx.x < st) red[threadIdx.x] += red[threadIdx.x + st];
        __syncthreads();
    }
    float scale = rsqrtf(red[0] / (float)CD + CEPS);
    for (int d = threadIdx.x; d < CD; d += 256)
        out[(size_t)t * CD + d] = row[d] * scale * w[d];
}

__global__ void rmsnorm_bf_kernel(const float* __restrict__ in,
                                  const float* __restrict__ w,
                                  float* __restrict__ out,
                                  __nv_bfloat16* __restrict__ outb) {
    int t = blockIdx.x;
    const float* row = in + (size_t)t * CD;
    float ss = 0.f;
    for (int d = threadIdx.x; d < CD; d += 256) { float v = row[d]; ss += v * v; }
    __shared__ float red[256];
    red[threadIdx.x] = ss; __syncthreads();
    for (int st = 128; st > 0; st >>= 1) {
        if (threadIdx.x < st) red[threadIdx.x] += red[threadIdx.x + st];
        __syncthreads();
    }
    float scale = rsqrtf(red[0] / (float)CD + CEPS);
    for (int d = threadIdx.x; d < CD; d += 256) {
        float v = row[d] * scale * w[d];
        out[(size_t)t * CD + d] = v;
        outb[(size_t)t * CD + d] = __float2bfloat16(v);
    }
}

// ---------------- scalar GEMM (router: exact fp32 feeds top-k) -------
__global__ void gemm64(const float* __restrict__ A, const float* __restrict__ Bm,
                       const float* __restrict__ res, float* __restrict__ C,
                       int M, int N, int K) {
    __shared__ float As[16][65];
    __shared__ float Bs[16][64];
    int tid = threadIdx.x;
    int tx = tid & 15, ty = tid >> 4;
    int m0 = blockIdx.y * 64, n0 = blockIdx.x * 64;
    int arow = tid >> 2;
    int acol = (tid & 3) * 4;
    int blin = tid * 4;
    int brow = blin >> 6;
    int bcol = blin & 63;
    const float* Aptr = A + (size_t)(m0 + arow) * K + acol;
    const float* Bptr = Bm + (size_t)brow * N + n0 + bcol;
    float acc[4][4] = {};
    for (int k0 = 0; k0 < K; k0 += 16) {
        float4 av = *(const float4*)(Aptr + k0);
        float4 bv = *(const float4*)(Bptr + (size_t)k0 * N);
        As[acol + 0][arow] = av.x; As[acol + 1][arow] = av.y;
        As[acol + 2][arow] = av.z; As[acol + 3][arow] = av.w;
        *(float4*)&Bs[brow][bcol] = bv;
        __syncthreads();
#pragma unroll
        for (int kk = 0; kk < 16; kk++) {
            float a[4], b[4];
#pragma unroll
            for (int i = 0; i < 4; i++) a[i] = As[kk][ty * 4 + i];
#pragma unroll
            for (int j = 0; j < 4; j++) b[j] = Bs[kk][tx * 4 + j];
#pragma unroll
            for (int i = 0; i < 4; i++)
#pragma unroll
                for (int j = 0; j < 4; j++) acc[i][j] += a[i] * b[j];
        }
        __syncthreads();
    }
#pragma unroll
    for (int i = 0; i < 4; i++)
#pragma unroll
        for (int j = 0; j < 4; j++) {
            size_t idx = (size_t)(m0 + ty * 4 + i) * N + n0 + tx * 4 + j;
            C[idx] = acc[i][j] + (res ? res[idx] : 0.f);
        }
}

// ---------------- fragment types ----------------
using FragAT = wmma::fragment<wmma::matrix_a, 16, 16, 8, wmma::precision::tf32, wmma::row_major>;
using FragBT = wmma::fragment<wmma::matrix_b, 16, 16, 8, wmma::precision::tf32, wmma::row_major>;
using FragAB = wmma::fragment<wmma::matrix_a, 16, 16, 16, __nv_bfloat16, wmma::row_major>;
using FragBB = wmma::fragment<wmma::matrix_b, 16, 16, 16, __nv_bfloat16, wmma::row_major>;
using FragC  = wmma::fragment<wmma::accumulator, 16, 16, 8, float>;
using FragCB = wmma::fragment<wmma::accumulator, 16, 16, 16, float>;

__device__ __forceinline__ void ld_at(FragAT& f, const float* p, int ld) {
    wmma::load_matrix_sync(f, p, ld);
#pragma unroll
    for (int i = 0; i < f.num_elements; i++) f.x[i] = wmma::__float_to_tf32(f.x[i]);
}
__device__ __forceinline__ void ld_bt(FragBT& f, const float* p, int ld) {
    wmma::load_matrix_sync(f, p, ld);
#pragma unroll
    for (int i = 0; i < f.num_elements; i++) f.x[i] = wmma::__float_to_tf32(f.x[i]);
}

// ================= pipelined TF32 dense GEMM (2 CTAs/SM) =================
constexpr int SM_TF32 = 2*128*36*4 + 2*32*68*4;   // 54272

__global__ __launch_bounds__(256, 2)
void gemm_tf32_pipe(const float* __restrict__ A, const float* __restrict__ B,
                    const float* __restrict__ res, float* __restrict__ C,
                    int M, int N, int K) {
    extern __shared__ char smraw[];
    float (*As)[128][36] = (float(*)[128][36])smraw;
    float (*Bs)[32][68]  = (float(*)[32][68])(smraw + 2*128*36*4);
    int tid = threadIdx.x;
    int w = tid >> 5, wm = w & 3, wn = w >> 2;
    int m0 = blockIdx.y * 128, n0 = blockIdx.x * 64;

    int a_row = tid >> 3, a_c4 = (tid & 7) * 4;
    int b_row = tid >> 4, b_c4 = (tid & 15) * 4;

    FragC acc[2][2];
#pragma unroll
    for (int i = 0; i < 2; i++)
#pragma unroll
        for (int j = 0; j < 2; j++) wmma::fill_fragment(acc[i][j], 0.f);

    float4 ra[4], rb[2];
    int nk = K / 32;
#pragma unroll
    for (int it = 0; it < 4; it++)
        ra[it] = *(const float4*)&A[(size_t)(m0 + a_row + it * 32) * K + a_c4];
#pragma unroll
    for (int it = 0; it < 2; it++)
        rb[it] = *(const float4*)&B[(size_t)(b_row + it * 16) * N + n0 + b_c4];
#pragma unroll
    for (int it = 0; it < 4; it++) *(float4*)&As[0][a_row + it * 32][a_c4] = ra[it];
#pragma unroll
    for (int it = 0; it < 2; it++) *(float4*)&Bs[0][b_row + it * 16][b_c4] = rb[it];
    __syncthreads();

    for (int k = 0; k < nk; k++) {
        int cur = k & 1;
        if (k + 1 < nk) {
            int k0 = (k + 1) * 32;
#pragma unroll
            for (int it = 0; it < 4; it++)
                ra[it] = *(const float4*)&A[(size_t)(m0 + a_row + it * 32) * K + k0 + a_c4];
#pragma unroll
            for (int it = 0; it < 2; it++)
                rb[it] = *(const float4*)&B[(size_t)(k0 + b_row + it * 16) * N + n0 + b_c4];
        }
#pragma unroll
        for (int kk = 0; kk < 4; kk++) {
            FragAT a[2]; FragBT b[2];
#pragma unroll
            for (int i = 0; i < 2; i++) ld_at(a[i], &As[cur][wm * 32 + i * 16][kk * 8], 36);
#pragma unroll
            for (int j = 0; j < 2; j++) ld_bt(b[j], &Bs[cur][kk * 8][wn * 32 + j * 16], 68);
#pragma unroll
            for (int i = 0; i < 2; i++)
#pragma unroll
                for (int j = 0; j < 2; j++) wmma::mma_sync(acc[i][j], a[i], b[j], acc[i][j]);
        }
        if (k + 1 < nk) {
            int nxt = cur ^ 1;
#pragma unroll
            for (int it = 0; it < 4; it++) *(float4*)&As[nxt][a_row + it * 32][a_c4] = ra[it];
#pragma unroll
            for (int it = 0; it < 2; it++) *(float4*)&Bs[nxt][b_row + it * 16][b_c4] = rb[it];
        }
        __syncthreads();
    }
#pragma unroll
    for (int i = 0; i < 2; i++)
#pragma unroll
        for (int j = 0; j < 2; j++) {
            size_t co = (size_t)(m0 + wm * 32 + i * 16) * N + n0 + wn * 32 + j * 16;
            if (res) {
                FragC r;
                wmma::load_matrix_sync(r, res + co, N, wmma::mem_row_major);
#pragma unroll
                for (int e2 = 0; e2 < r.num_elements; e2++) acc[i][j].x[e2] += r.x[e2];
            }
            wmma::store_matrix_sync(C + co, acc[i][j], N, wmma::mem_row_major);
        }
}

// ---------------- per-head q/k rmsnorm + rope ----------------
__global__ void qknorm_rope_kernel(const float* __restrict__ cos_,
                                   const float* __restrict__ sin_,
                                   const float* __restrict__ qn_w,
                                   const float* __restrict__ kn_w) {
    int t = blockIdx.x;
    int hy = blockIdx.y;
    int d = threadIdx.x;
    float* ptr; const float* w;
    if (hy < CH) { ptr = g_q + ((size_t)t * CH + hy) * CHD;          w = qn_w; }
    else         { ptr = g_k + ((size_t)t * CKVH + (hy - CH)) * CHD; w = kn_w; }
    float v = ptr[d];
    float ss = v * v;
#pragma unroll
    for (int off = 16; off > 0; off >>= 1) ss += __shfl_xor_sync(0xffffffffu, ss, off);
    __shared__ float ws[4];
    if ((d & 31) == 0) ws[d >> 5] = ss;
    __syncthreads();
    float tot = ws[0] + ws[1] + ws[2] + ws[3];
    float nrm = v * rsqrtf(tot / (float)CHD + CEPS) * w[d];
    __shared__ float nbuf[128];
    nbuf[d] = nrm;
    __syncthreads();
    float rot = (d < 64) ? -nbuf[d + 64] : nbuf[d - 64];
    float c = cos_[(size_t)t * CHD + d];
    float s = sin_[(size_t)t * CHD + d];
    ptr[d] = nrm * c + rot * s;
}

// ---------------- flash attention (causal, GQA), exact fp32 ----------------
__global__ void attn_kernel() {
    int qt = blockIdx.x;
    int h  = blockIdx.y;
    int b  = blockIdx.z;
    int kvh = h / (CH / CKVH);
    int tid = threadIdx.x;
    int r  = tid >> 2;
    int qd = tid & 3;
    __shared__ float Qs[32][128];
    __shared__ float KVs[32][128];
    __shared__ float Ss[32][33];

    for (int i = tid; i < 32 * 128; i += 128) {
        int rr = i >> 7, dd = i & 127;
        Qs[rr][dd] = g_q[((size_t)(b * CS + qt * 32 + rr) * CH + h) * CHD + dd];
    }
    float acc[32];
#pragma unroll
    for (int i = 0; i < 32; i++) acc[i] = 0.f;
    float m = -1e30f, l = 0.f;
    const float scale = 0.088388347648318447f;

    for (int jt = 0; jt <= qt; jt++) {
        __syncthreads();
        for (int i = tid; i < 32 * 128; i += 128) {
            int rr = i >> 7, dd = i & 127;
            KVs[rr][dd] = g_k[((size_t)(b * CS + jt * 32 + rr) * CKVH + kvh) * CHD + dd];
        }
        __syncthreads();
        float sc[8];
#pragma unroll
        for (int jj = 0; jj < 8; jj++) sc[jj] = 0.f;
        for (int dd = 0; dd < 128; dd++) {
            float qv = Qs[r][dd];
#pragma unroll
            for (int jj = 0; jj < 8; jj++) sc[jj] += qv * KVs[qd * 8 + jj][dd];
        }
        int qg = qt * 32 + r;
#pragma unroll
        for (int jj = 0; jj < 8; jj++) {
            int kg = jt * 32 + qd * 8 + jj;
            float v = sc[jj] * scale;
            if (kg > qg) v = -1e30f;
            Ss[r][qd * 8 + jj] = v;
        }
        __syncthreads();
        float tm = m;
#pragma unroll
        for (int c = 0; c < 32; c++) tm = fmaxf(tm, Ss[r][c]);
        float alpha = expf(m - tm);
        float p[32];
        float lsum = 0.f;
#pragma unroll
        for (int c = 0; c < 32; c++) { p[c] = expf(Ss[r][c] - tm); lsum += p[c]; }
        l = l * alpha + lsum;
        m = tm;
        __syncthreads();
        for (int i = tid; i < 32 * 128; i += 128) {
            int rr = i >> 7, dd = i & 127;
            KVs[rr][dd] = g_v[((size_t)(b * CS + jt * 32 + rr) * CKVH + kvh) * CHD + dd];
        }
        __syncthreads();
#pragma unroll
        for (int dd = 0; dd < 32; dd++) acc[dd] *= alpha;
        for (int c = 0; c < 32; c++) {
            float pv = p[c];
#pragma unroll
            for (int dd = 0; dd < 32; dd++) acc[dd] += pv * KVs[c][qd * 32 + dd];
        }
    }
    float inv = 1.f / l;
    int t = b * CS + qt * 32 + r;
#pragma unroll
    for (int dd = 0; dd < 32; dd++)
        g_o[((size_t)t * CH + h) * CHD + qd * 32 + dd] = acc[dd] * inv;
}

// ---------------- router softmax + top-8 ----------------
__global__ void topk_kernel() {
    int t = blockIdx.x, e = threadIdx.x;
    __shared__ float red[64];
    __shared__ int   redi[64];
    __shared__ float tv[8];
    __shared__ int   ti[8];
    float lg = g_logits[t * CE + e];
    red[e] = lg; __syncthreads();
    for (int st = 32; st > 0; st >>= 1) {
        if (e < st) red[e] = fmaxf(red[e], red[e + st]);
        __syncthreads();
    }
    float mx = red[0]; __syncthreads();
    float ex = expf(lg - mx);
    red[e] = ex; __syncthreads();
    for (int st = 32; st > 0; st >>= 1) {
        if (e < st) red[e] += red[e + st];
        __syncthreads();
    }
    float sum = red[0]; __syncthreads();
    float sel = ex / sum;
    for (int k = 0; k < 8; k++) {
        red[e] = sel; redi[e] = e; __syncthreads();
        for (int st = 32; st > 0; st >>= 1) {
            if (e < st) {
                if (red[e + st] > red[e]) { red[e] = red[e + st]; redi[e] = redi[e + st]; }
            }
            __syncthreads();
        }
        if (e == 0) { tv[k] = red[0]; ti[k] = redi[0]; }
        __syncthreads();
        if (e == ti[k]) sel = -1.f;
        __syncthreads();
    }
    if (e < 8) {
        float s8 = 0.f;
#pragma unroll
        for (int k = 0; k < 8; k++) s8 += tv[k];
        g_topi[t * CK + e] = ti[e];
        g_topw[t * CK + e] = tv[e] / s8;
    }
}

// ---------------- routing bookkeeping ----------------
__global__ void zero_counts_kernel() { if (threadIdx.x < CE) g_counts[threadIdx.x] = 0; }

__global__ void count_kernel() {
    int i = blockIdx.x * blockDim.x + threadIdx.x;
    if (i < NSLOT) atomicAdd(&g_counts[g_topi[i]], 1);
}

__global__ void scan_kernel() {
    int acc = 0;
    for (int e = 0; e < CE; e++) {
        g_offsets[e] = acc;
        g_cursor[e]  = acc;
        acc += ((g_counts[e] + 127) >> 7) << 7;
    }
}

__global__ void init_slots_kernel() {
    int i = blockIdx.x * blockDim.x + threadIdx.x;
    if (i < PADTOT) g_slot_token[i] = 0;
}

__global__ void fill_kernel() {
    int i = blockIdx.x * blockDim.x + threadIdx.x;
    if (i < NSLOT) {
        int e = g_topi[i];
        int p = atomicAdd(&g_cursor[e], 1);
        g_slot_token[p] = i >> 3;
        g_pos_of[i] = p;
    }
}

// ================= unified MoE bf16 GEMM (2 CTAs/SM) =================
// MODE 0: gate  = ht_bf(gathered) @ w_gate -> g_gate (fp32)
// MODE 1: up    = ht_bf(gathered) @ w_up; epilogue act_bf = silu(g_gate)*u
// MODE 2: down  = act_bf @ w_down -> g_y (fp32)
// BM=128 BN=64 BK=32, 256 threads, double-buffered.
// smem: As bf16[2][128][40] @0 (20480) | Bs bf16[2][32][72] @20480 (9216)
//       stok int[128] @29696 (512) | scr f32[8][16][16] @30208 (8192) = 38400
constexpr int SM_MOE = 38400;

template<int MODE>
__global__ __launch_bounds__(256, 2)
void moe_gemm_bf16(const float* __restrict__ W) {
    extern __shared__ char smraw[];
    __nv_bfloat16 (*As)[128][40] = (__nv_bfloat16(*)[128][40])smraw;
    __nv_bfloat16 (*Bs)[32][72]  = (__nv_bfloat16(*)[32][72])(smraw + 20480);
    int* stok = (int*)(smraw + 29696);
    float (*scr)[16][16] = (float(*)[16][16])(smraw + 30208);

    constexpr int KDIM = (MODE == 2) ? CF : CD;
    constexpr int NDIM = (MODE == 2) ? CD : CF;

    int e = blockIdx.y;
    int n0 = blockIdx.x * 64;
    int off = g_offsets[e], cnt = g_counts[e];
    int ntiles = (cnt + 127) >> 7;
    const float* Bm = W + (size_t)e * KDIM * NDIM;

    int tid = threadIdx.x;
    int w = tid >> 5, wm = w & 3, wn = w >> 2;
    int lane = tid & 31;
    int b_row = tid >> 4, b_c4 = (tid & 15) * 4;

    for (int rt = 0; rt < ntiles; rt++) {
        size_t abase = (size_t)(off + rt * 128);
        if (MODE < 2) {
            if (tid < 128) stok[tid] = g_slot_token[abase + tid];
            __syncthreads();
        }

        FragCB acc[2][2];
#pragma unroll
        for (int i = 0; i < 2; i++)
#pragma unroll
            for (int j = 0; j < 2; j++) wmma::fill_fragment(acc[i][j], 0.f);

        uint4 raA[2]; float4 rb[2];
        constexpr int nk = KDIM / 32;
        // prologue
#pragma unroll
        for (int it = 0; it < 2; it++) {
            int i = tid + it * 256;
            int row = i >> 2, c8 = (i & 3) * 8;
            if (MODE < 2)
                raA[it] = *(const uint4*)&g_ht_bf[(size_t)stok[row] * CD + c8];
            else
                raA[it] = *(const uint4*)&g_act_bf[(abase + row) * CF + c8];
        }
#pragma unroll
        for (int it = 0; it < 2; it++)
            rb[it] = *(const float4*)&Bm[(size_t)(b_row + it * 16) * NDIM + n0 + b_c4];
#pragma unroll
        for (int it = 0; it < 2; it++) {
            int i = tid + it * 256;
            int row = i >> 2, c8 = (i & 3) * 8;
            *(uint4*)&As[0][row][c8] = raA[it];
        }
#pragma unroll
        for (int it = 0; it < 2; it++)
            st_bf4(&Bs[0][b_row + it * 16][b_c4], rb[it]);
        __syncthreads();

        for (int k = 0; k < nk; k++) {
            int cur = k & 1;
            if (k + 1 < nk) {
                int k0 = (k + 1) * 32;
#pragma unroll
                for (int it = 0; it < 2; it++) {
                    int i = tid + it * 256;
                    int row = i >> 2, c8 = (i & 3) * 8;
                    if (MODE < 2)
                        raA[it] = *(const uint4*)&g_ht_bf[(size_t)stok[row] * CD + k0 + c8];
                    else
                        raA[it] = *(const uint4*)&g_act_bf[(abase + row) * CF + k0 + c8];
                }
#pragma unroll
                for (int it = 0; it < 2; it++)
                    rb[it] = *(const float4*)&Bm[(size_t)(k0 + b_row + it * 16) * NDIM + n0 + b_c4];
            }
#pragma unroll
            for (int kk = 0; kk < 2; kk++) {
                FragAB a[2]; FragBB b[2];
#pragma unroll
                for (int i = 0; i < 2; i++)
                    wmma::load_matrix_sync(a[i], &As[cur][wm * 32 + i * 16][kk * 16], 40);
#pragma unroll
                for (int j = 0; j < 2; j++)
                    wmma::load_matrix_sync(b[j], &Bs[cur][kk * 16][wn * 32 + j * 16], 72);
#pragma unroll
                for (int i = 0; i < 2; i++)
#pragma unroll
                    for (int j = 0; j < 2; j++) wmma::mma_sync(acc[i][j], a[i], b[j], acc[i][j]);
            }
            if (k + 1 < nk) {
                int nxt = cur ^ 1;
#pragma unroll
                for (int it = 0; it < 2; it++) {
                    int i = tid + it * 256;
                    int row = i >> 2, c8 = (i & 3) * 8;
                    *(uint4*)&As[nxt][row][c8] = raA[it];
                }
#pragma unroll
                for (int it = 0; it < 2; it++)
                    st_bf4(&Bs[nxt][b_row + it * 16][b_c4], rb[it]);
            }
            __syncthreads();
        }

        // epilogue
        if (MODE == 0) {
#pragma unroll
            for (int i = 0; i < 2; i++)
#pragma unroll
                for (int j = 0; j < 2; j++) {
                    float* cp = g_gate + (abase + wm * 32 + i * 16) * CF + n0 + wn * 32 + j * 16;
                    wmma::store_matrix_sync(cp, acc[i][j], CF, wmma::mem_row_major);
                }
        } else if (MODE == 2) {
#pragma unroll
            for (int i = 0; i < 2; i++)
#pragma unroll
                for (int j = 0; j < 2; j++) {
                    float* cp = g_y + (abase + wm * 32 + i * 16) * CD + n0 + wn * 32 + j * 16;
                    wmma::store_matrix_sync(cp, acc[i][j], CD, wmma::mem_row_major);
                }
        } else {
            // up: act = silu(gate) * u  -> bf16
#pragma unroll
            for (int i = 0; i < 2; i++)
#pragma unroll
                for (int j = 0; j < 2; j++) {
                    wmma::store_matrix_sync(&scr[w][0][0], acc[i][j], 16, wmma::mem_row_major);
                    __syncwarp();
                    {
                        int r = lane >> 1, cb = (lane & 1) * 8;
                        size_t grow = abase + wm * 32 + i * 16 + r;
                        int col = n0 + wn * 32 + j * 16 + cb;
                        const float* gp = &g_gate[grow * CF + col];
                        float4 g0 = *(const float4*)gp;
                        float4 g1 = *(const float4*)(gp + 4);
                        float4 u0 = *(float4*)&scr[w][r][cb];
                        float4 u1 = *(float4*)&scr[w][r][cb + 4];
                        float4 o0, o1;
                        o0.x = (g0.x / (1.f + expf(-g0.x))) * u0.x;
                        o0.y = (g0.y / (1.f + expf(-g0.y))) * u0.y;
                        o0.z = (g0.z / (1.f + expf(-g0.z))) * u0.z;
                        o0.w = (g0.w / (1.f + expf(-g0.w))) * u0.w;
                        o1.x = (g1.x / (1.f + expf(-g1.x))) * u1.x;
                        o1.y = (g1.y / (1.f + expf(-g1.y))) * u1.y;
                        o1.z = (g1.z / (1.f + expf(-g1.z))) * u1.z;
                        o1.w = (g1.w / (1.f + expf(-g1.w))) * u1.w;
                        __nv_bfloat16* dst = g_act_bf + grow * CF + col;
                        st_bf4(dst, o0);
                        st_bf4(dst + 4, o1);
                    }
                    __syncwarp();
                }
        }
        __syncthreads();
    }
}

// ---------------- final combine ----------------
__global__ void final_add_kernel(float* __restrict__ out) {
    int t = blockIdx.x;
    __shared__ int   pos[8];
    __shared__ float w[8];
    if (threadIdx.x < 8) {
        pos[threadIdx.x] = g_pos_of[t * CK + threadIdx.x];
        w[threadIdx.x]   = g_topw[t * CK + threadIdx.x];
    }
    __syncthreads();
    for (int d = threadIdx.x; d < CD; d += 256) {
        float acc = out[(size_t)t * CD + d];
#pragma unroll
        for (int k = 0; k < 8; k++)
            acc += w[k] * g_y[(size_t)pos[k] * CD + d];
        out[(size_t)t * CD + d] = acc;
    }
}

// ---------------- launch ----------------
extern "C" void kernel_launch(void* const* d_in, const int* in_sizes, int n_in,
                              void* d_out, int out_size) {
    const float* x        = (const float*)d_in[0];
    const float* cos_     = (const float*)d_in[1];
    const float* sin_     = (const float*)d_in[2];
    const float* ln1_w    = (const float*)d_in[3];
    const float* wq       = (const float*)d_in[4];
    const float* wk       = (const float*)d_in[5];
    const float* wv       = (const float*)d_in[6];
    const float* wo       = (const float*)d_in[7];
    const float* qn_w     = (const float*)d_in[8];
    const float* kn_w     = (const float*)d_in[9];
    const float* ln2_w    = (const float*)d_in[10];
    const float* router_w = (const float*)d_in[11];
    const float* w_gate   = (const float*)d_in[12];
    const float* w_up     = (const float*)d_in[13];
    const float* w_down   = (const float*)d_in[14];
    float* out = (float*)d_out;

    cudaFuncSetAttribute(gemm_tf32_pipe,   cudaFuncAttributeMaxDynamicSharedMemorySize, SM_TF32);
    cudaFuncSetAttribute(moe_gemm_bf16<0>, cudaFuncAttributeMaxDynamicSharedMemorySize, SM_MOE);
    cudaFuncSetAttribute(moe_gemm_bf16<1>, cudaFuncAttributeMaxDynamicSharedMemorySize, SM_MOE);
    cudaFuncSetAttribute(moe_gemm_bf16<2>, cudaFuncAttributeMaxDynamicSharedMemorySize, SM_MOE);

    float *p_h, *p_q, *p_k, *p_v, *p_o, *p_ht, *p_logits;
    __nv_bfloat16 *p_ht_bf;
    cudaGetSymbolAddress((void**)&p_h,  g_h);
    cudaGetSymbolAddress((void**)&p_q,  g_q);
    cudaGetSymbolAddress((void**)&p_k,  g_k);
    cudaGetSymbolAddress((void**)&p_v,  g_v);
    cudaGetSymbolAddress((void**)&p_o,  g_o);
    cudaGetSymbolAddress((void**)&p_ht, g_ht);
    cudaGetSymbolAddress((void**)&p_ht_bf, g_ht_bf);
    cudaGetSymbolAddress((void**)&p_logits, g_logits);

    // 1. h = rmsnorm(x)
    rmsnorm_kernel<<<CT, 256>>>(x, ln1_w, p_h);
    // 2. q,k,v projections (pipelined TF32, 2 CTAs/SM)
    gemm_tf32_pipe<<<dim3((CH * CHD) / 64, CT / 128), 256, SM_TF32>>>(p_h, wq, nullptr, p_q, CT, CH * CHD, CD);
    gemm_tf32_pipe<<<dim3((CKVH * CHD) / 64, CT / 128), 256, SM_TF32>>>(p_h, wk, nullptr, p_k, CT, CKVH * CHD, CD);
    gemm_tf32_pipe<<<dim3((CKVH * CHD) / 64, CT / 128), 256, SM_TF32>>>(p_h, wv, nullptr, p_v, CT, CKVH * CHD, CD);
    // 3. per-head q/k rmsnorm + rope
    qknorm_rope_kernel<<<dim3(CT, CH + CKVH), 128>>>(cos_, sin_, qn_w, kn_w);
    // 4. attention (exact fp32)
    attn_kernel<<<dim3(CS / 32, CH, CB), 128>>>();
    // 5. out = o @ wo + x
    gemm_tf32_pipe<<<dim3(CD / 64, CT / 128), 256, SM_TF32>>>(p_o, wo, x, out, CT, CD, CD);
    // 6. ht = rmsnorm(out), fp32 + bf16
    rmsnorm_bf_kernel<<<CT, 256>>>(out, ln2_w, p_ht, p_ht_bf);
    // 7. router logits (exact fp32) + top-8
    gemm64<<<dim3(CE / 64, CT / 64), 256>>>(p_ht, router_w, nullptr, p_logits, CT, CE, CD);
    topk_kernel<<<CT, 64>>>();
    // 8. routing bookkeeping
    zero_counts_kernel<<<1, 64>>>();
    count_kernel<<<NSLOT / 256, 256>>>();
    scan_kernel<<<1, 1>>>();
    init_slots_kernel<<<PADTOT / 256, 256>>>();
    fill_kernel<<<NSLOT / 256, 256>>>();
    // 9. MoE: gate, up(+silu), down  (bf16, 2 CTAs/SM)
    moe_gemm_bf16<0><<<dim3(CF / 64, CE), 256, SM_MOE>>>(w_gate);
    moe_gemm_bf16<1><<<dim3(CF / 64, CE), 256, SM_MOE>>>(w_up);
    moe_gemm_bf16<2><<<dim3(CD / 64, CE), 256, SM_MOE>>>(w_down);
    // 10. deterministic per-token combine
    final_add_kernel<<<CT, 256>>>(out);
}